// round 15
// baseline (speedup 1.0000x reference)
#include <cuda_runtime.h>
#include <cuda_bf16.h>
#include <cstdint>

// Problem constants
#define B_ 4
#define C_ 64
#define T_ 8
#define X_ 96
#define Y_ 96
#define S_ 9216            // X_*Y_
#define N_ 36864           // B_*S_
#define TS_ 73728          // T_*S_
#define TOTAL_ 18874368    // B_*C_*T_*S_
#define QSZ_ 18874368      // T_*C_*N_
#define CNT_ 294912.0f     // B_*T_*S_

// -------- scratch (device globals; no runtime allocation) --------
__device__ __nv_bfloat16 g_xh[TOTAL_];            // conv0 raw output (pre-BN0), bf16
__device__ __nv_bfloat16 g_qkvh[3 * QSZ_];        // q,k,v bf16, [z][t][c][n]
__device__ __nv_bfloat16 g_zh[TOTAL_];            // residual + out_proj (pre-BN1), bf16
__device__ float g_sum0[128];
__device__ float g_sum1[128];
__device__ float g_m[B_ * C_ * T_];
__device__ __align__(16) __nv_bfloat16 g_wk[64 * 576];   // conv0 [co][k], k=tap*64+ci
__device__ __align__(16) __nv_bfloat16 g_wqkv[192 * 64]; // in_proj bf16
__device__ __align__(16) __nv_bfloat16 g_wout[64 * 64];  // out_proj bf16

__device__ __forceinline__ float lk(float v) { return v >= 0.f ? v : 0.01f * v; }

// FFMA-only exp
__device__ __forceinline__ float fexp(float x) {
    const float L2E = 1.4426950408889634f;
    float t = fmaf(x, L2E, 12582912.0f);
    int ii = __float_as_int(t) - 0x4B400000;
    float i = t - 12582912.0f;
    float f = fmaf(x, L2E, -i);
    float p = 1.3333558146e-3f;
    p = fmaf(p, f, 9.6181291918e-3f);
    p = fmaf(p, f, 5.5504108664e-2f);
    p = fmaf(p, f, 2.4022650695e-1f);
    p = fmaf(p, f, 6.9314718056e-1f);
    p = fmaf(p, f, 1.0f);
    return __int_as_float(__float_as_int(p) + (ii << 23));
}

__device__ __forceinline__ float bflo(uint32_t u) { return __int_as_float(u << 16); }
__device__ __forceinline__ float bfhi(uint32_t u) { return __int_as_float(u & 0xFFFF0000u); }

__device__ __forceinline__ void mma_bf16(float* c, uint32_t a0, uint32_t a1,
                                         uint32_t a2, uint32_t a3,
                                         uint32_t b0, uint32_t b1) {
    asm volatile(
        "mma.sync.aligned.m16n8k16.row.col.f32.bf16.bf16.f32 "
        "{%0,%1,%2,%3}, {%4,%5,%6,%7}, {%8,%9}, {%0,%1,%2,%3};"
        : "+f"(c[0]), "+f"(c[1]), "+f"(c[2]), "+f"(c[3])
        : "r"(a0), "r"(a1), "r"(a2), "r"(a3), "r"(b0), "r"(b1));
}

__device__ __forceinline__ uint32_t packbf(float a, float b) {
    __nv_bfloat162 p = __floats2bfloat162_rn(a, b);
    return *(uint32_t*)&p;
}

__device__ __forceinline__ uint32_t smem_u32(const void* p) {
    uint32_t a;
    asm("{ .reg .u64 t; cvta.to.shared.u64 t, %1; cvt.u32.u64 %0, t; }" : "=r"(a) : "l"(p));
    return a;
}

__device__ __forceinline__ void ldsm_x4(uint32_t* r, uint32_t addr) {
    asm volatile("ldmatrix.sync.aligned.m8n8.x4.shared.b16 {%0,%1,%2,%3}, [%4];"
        : "=r"(r[0]), "=r"(r[1]), "=r"(r[2]), "=r"(r[3]) : "r"(addr));
}
__device__ __forceinline__ void ldsm_x4_t(uint32_t* r, uint32_t addr) {
    asm volatile("ldmatrix.sync.aligned.m8n8.x4.trans.shared.b16 {%0,%1,%2,%3}, [%4];"
        : "=r"(r[0]), "=r"(r[1]), "=r"(r[2]), "=r"(r[3]) : "r"(addr));
}

// ===================== combined prep =====================
__global__ void k_prep(const float* __restrict__ w, const float* __restrict__ inW,
                       const float* __restrict__ outW) {
    int i = blockIdx.x * 256 + threadIdx.x;
    if (i < 128) { g_sum0[i] = 0.f; g_sum1[i] = 0.f; }
    if (i < 64 * 576) {
        int co = i / 576, k = i - co * 576;
        g_wk[i] = __float2bfloat16(w[(co * 64 + (k & 63)) * 9 + (k >> 6)]);
    }
    if (i < 192 * 64) g_wqkv[i] = __float2bfloat16(inW[i]);
    if (i < 64 * 64) g_wout[i] = __float2bfloat16(outW[i]);
}

// ===================== conv0: pipelined bf16 mma + ldmatrix, 512 thr =====================
#define SINW 72
#define ROWE (98 * SINW)
#define RING 8
#define WKS 584
#define SM_WK_OFF (RING * ROWE * 2)
#define SM_CONV_TOT (SM_WK_OFF + 64 * WKS * 2)

__device__ __forceinline__ void stage_row(__nv_bfloat16* sin_s, const float* hb,
                                          int gx, int tid) {
    const int slot = (gx + 8) & 7;
    __nv_bfloat16* dst = sin_s + slot * ROWE;
    if ((unsigned)gx >= 96u) {
        for (int e = tid; e < 6144; e += 512) {
            int ci = e / 96, y = e - ci * 96;
            dst[(y + 1) * SINW + ci] = __float2bfloat16(0.f);
        }
    } else {
        const float* hp = hb + (size_t)gx * 96;
        for (int e = tid; e < 6144; e += 512) {
            int ci = e / 96, y = e - ci * 96;
            dst[(y + 1) * SINW + ci] = __float2bfloat16(hp[(size_t)ci * TS_ + y]);
        }
    }
    if (tid < 64) dst[tid] = __float2bfloat16(0.f);
    else if (tid < 128) dst[97 * SINW + (tid - 64)] = __float2bfloat16(0.f);
}

__global__ void __launch_bounds__(512)
k_conv0_mma(const float* __restrict__ h, const float* __restrict__ bias) {
    extern __shared__ char smem[];
    __nv_bfloat16* sin_s = (__nv_bfloat16*)smem;
    __nv_bfloat16* wk_s = (__nv_bfloat16*)(smem + SM_WK_OFF);
    __shared__ float s_st[128];

    const int tid = threadIdx.x, lane = tid & 31, wid = tid >> 5;
    const int group = blockIdx.x, bt = blockIdx.y, b = bt >> 3, t = bt & 7;
    const float* hb = h + (size_t)b * (64 * TS_) + (size_t)t * S_;

    if (tid < 128) s_st[tid] = 0.f;
    {
        const uint4* src = (const uint4*)g_wk;
        for (int e = tid; e < 4608; e += 512) {
            int co = e / 72, q = e - co * 72;
            *(uint4*)&wk_s[co * WKS + q * 8] = src[e];
        }
    }
    {
        const int p0 = group * 2304;
        const int xlo = p0 / 96, xhi = (p0 + 255) / 96;
        for (int gx = xlo - 1; gx <= xhi + 1; gx++) stage_row(sin_s, hb, gx, tid);
    }
    __syncthreads();

    const int mg = wid >> 1, nh = wid & 1;
    const int g = lane >> 2, tg = lane & 3;

    const uint32_t sin_b = smem_u32(sin_s);
    const uint32_t wk_b = smem_u32(wk_s);

    uint32_t wkaddr[2];
    {
        const int koff = ((lane >> 3) & 1) * 8;
        const int cosub = (lane & 7) + ((lane >> 4) & 1) * 8;
#pragma unroll
        for (int ntp = 0; ntp < 2; ntp++) {
            const int co = nh * 32 + ntp * 16 + cosub;
            wkaddr[ntp] = wk_b + (uint32_t)(co * WKS + koff) * 2;
        }
    }
    const uint32_t khiA = (uint32_t)((lane >> 4) * 16);

    float bv[4][2];
#pragma unroll
    for (int nt = 0; nt < 4; nt++) {
        const int co0 = nh * 32 + nt * 8 + tg * 2;
        bv[nt][0] = __ldg(&bias[co0]);
        bv[nt][1] = __ldg(&bias[co0 + 1]);
    }

    float st_s[8], st_q[8];
#pragma unroll
    for (int i = 0; i < 8; i++) { st_s[i] = 0.f; st_q[i] = 0.f; }

    __nv_bfloat16* obB = g_xh + (size_t)b * (64 * TS_) + (size_t)t * S_;

    for (int ti = 0; ti < 9; ti++) {
        const int p0 = group * 2304 + ti * 256;
        const int xhi = (p0 + 255) / 96;
        if (ti < 8) {
            const int xhin = (p0 + 511) / 96;
            for (int gx = xhi + 2; gx <= xhin + 1; gx++) stage_row(sin_s, hb, gx, tid);
        }

        uint32_t aRB[2][3];
        {
            const int plbase = p0 + mg * 32 + (lane & 15);
#pragma unroll
            for (int mt = 0; mt < 2; mt++) {
                const int pl = plbase + mt * 16;
                const int px = pl / 96, py = pl - px * 96;
#pragma unroll
                for (int dx = 0; dx < 3; dx++)
                    aRB[mt][dx] = sin_b +
                        (uint32_t)(((px + dx + 7) & 7) * ROWE + py * SINW) * 2 + khiA;
            }
        }

        float acc[2][4][4];
#pragma unroll
        for (int mt = 0; mt < 2; mt++)
#pragma unroll
            for (int nt = 0; nt < 4; nt++)
#pragma unroll
                for (int i = 0; i < 4; i++) acc[mt][nt][i] = 0.f;

        // ---- software-pipelined (tap,kk) loop: 36 steps, double-buffered frags ----
        uint32_t fA0[2][4], fA1[2][4], fB0[2][4], fB1[2][4];
        {
            // prologue: step 0 (tap 0 = dx0,dy0; kk 0)
            ldsm_x4(fA0[0], aRB[0][0]);
            ldsm_x4(fA1[0], aRB[1][0]);
            ldsm_x4(fB0[0], wkaddr[0]);
            ldsm_x4(fB1[0], wkaddr[1]);
        }
#pragma unroll
        for (int idx = 0; idx < 36; idx++) {
            const int cur = idx & 1, nxt = cur ^ 1;
            if (idx < 35) {
                const int i1 = idx + 1;
                const int tap1 = i1 >> 2, kk1 = i1 & 3;
                const int dx1 = tap1 / 3, dy1 = tap1 - dx1 * 3;
                const uint32_t aoff = (uint32_t)(dy1 * SINW + kk1 * 16) * 2;
                const uint32_t bk = (uint32_t)(tap1 * 64 + kk1 * 16) * 2;
                ldsm_x4(fA0[nxt], aRB[0][dx1] + aoff);
                ldsm_x4(fA1[nxt], aRB[1][dx1] + aoff);
                ldsm_x4(fB0[nxt], wkaddr[0] + bk);
                ldsm_x4(fB1[nxt], wkaddr[1] + bk);
            }
            mma_bf16(acc[0][0], fA0[cur][0], fA0[cur][1], fA0[cur][2], fA0[cur][3], fB0[cur][0], fB0[cur][1]);
            mma_bf16(acc[1][0], fA1[cur][0], fA1[cur][1], fA1[cur][2], fA1[cur][3], fB0[cur][0], fB0[cur][1]);
            mma_bf16(acc[0][1], fA0[cur][0], fA0[cur][1], fA0[cur][2], fA0[cur][3], fB0[cur][2], fB0[cur][3]);
            mma_bf16(acc[1][1], fA1[cur][0], fA1[cur][1], fA1[cur][2], fA1[cur][3], fB0[cur][2], fB0[cur][3]);
            mma_bf16(acc[0][2], fA0[cur][0], fA0[cur][1], fA0[cur][2], fA0[cur][3], fB1[cur][0], fB1[cur][1]);
            mma_bf16(acc[1][2], fA1[cur][0], fA1[cur][1], fA1[cur][2], fA1[cur][3], fB1[cur][0], fB1[cur][1]);
            mma_bf16(acc[0][3], fA0[cur][0], fA0[cur][1], fA0[cur][2], fA0[cur][3], fB1[cur][2], fB1[cur][3]);
            mma_bf16(acc[1][3], fA1[cur][0], fA1[cur][1], fA1[cur][2], fA1[cur][3], fB1[cur][2], fB1[cur][3]);
        }

        __nv_bfloat16* ob = obB + p0;
#pragma unroll
        for (int nt = 0; nt < 4; nt++) {
            const int co0 = nh * 32 + nt * 8 + tg * 2;
#pragma unroll
            for (int mt = 0; mt < 2; mt++) {
                const int pr = mg * 32 + mt * 16 + g;
                float v0 = acc[mt][nt][0] + bv[nt][0];
                float v1 = acc[mt][nt][1] + bv[nt][1];
                float v2 = acc[mt][nt][2] + bv[nt][0];
                float v3 = acc[mt][nt][3] + bv[nt][1];
                ob[(size_t)co0 * TS_ + pr]           = __float2bfloat16(v0);
                ob[(size_t)(co0 + 1) * TS_ + pr]     = __float2bfloat16(v1);
                ob[(size_t)co0 * TS_ + pr + 8]       = __float2bfloat16(v2);
                ob[(size_t)(co0 + 1) * TS_ + pr + 8] = __float2bfloat16(v3);
                st_s[nt * 2]     += v0 + v2;
                st_q[nt * 2]     += v0 * v0 + v2 * v2;
                st_s[nt * 2 + 1] += v1 + v3;
                st_q[nt * 2 + 1] += v1 * v1 + v3 * v3;
            }
        }
        __syncthreads();
    }

#pragma unroll
    for (int i = 0; i < 8; i++) {
        st_s[i] += __shfl_xor_sync(0xffffffffu, st_s[i], 4);
        st_s[i] += __shfl_xor_sync(0xffffffffu, st_s[i], 8);
        st_s[i] += __shfl_xor_sync(0xffffffffu, st_s[i], 16);
        st_q[i] += __shfl_xor_sync(0xffffffffu, st_q[i], 4);
        st_q[i] += __shfl_xor_sync(0xffffffffu, st_q[i], 8);
        st_q[i] += __shfl_xor_sync(0xffffffffu, st_q[i], 16);
    }
    if (lane < 4) {
#pragma unroll
        for (int nt = 0; nt < 4; nt++)
#pragma unroll
            for (int r = 0; r < 2; r++) {
                const int co = nh * 32 + nt * 8 + lane * 2 + r;
                atomicAdd(&s_st[co], st_s[nt * 2 + r]);
                atomicAdd(&s_st[64 + co], st_q[nt * 2 + r]);
            }
    }
    __syncthreads();
    if (tid < 128) atomicAdd(&g_sum0[tid], s_st[tid]);
}

// ---------------- qkv (unchanged) ----------------
#define QSM_WS (2 * 128 * 72 * 2)
#define QSM_TOT (QSM_WS + 192 * 72 * 2)

__global__ void __launch_bounds__(512) k_qkv_mma(const float* __restrict__ bias,
                                                 const float* __restrict__ bn0g,
                                                 const float* __restrict__ bn0b) {
    extern __shared__ char smem[];
    __nv_bfloat16* Xt = (__nv_bfloat16*)smem;
    __nv_bfloat16* Ws = (__nv_bfloat16*)(smem + QSM_WS);
    __shared__ float s_c[128];
    const int tid = threadIdx.x, lane = tid & 31, wid = tid >> 5;
    const int group = blockIdx.x;
    const int bt = blockIdx.y, b = bt >> 3, t = bt & 7;

    if (tid < 64) {
        const float inv = 1.0f / CNT_;
        float mu = g_sum0[tid] * inv;
        float var = g_sum0[64 + tid] * inv - mu * mu;
        float A = bn0g[tid] * rsqrtf(var + 1e-5f);
        s_c[tid] = A;
        s_c[64 + tid] = bn0b[tid] - mu * A;
    }
    {
        const uint4* src = (const uint4*)g_wqkv;
        for (int e = tid; e < 1536; e += 512) {
            int co = e >> 3, q = e & 7;
            *(uint4*)&Ws[co * 72 + q * 8] = src[e];
        }
    }
    __syncthreads();

    const __nv_bfloat16* xbase = g_xh + ((size_t)(b * C_) * T_ + t) * S_;
    {
        const __nv_bfloat16* xb = xbase + group * 18 * 128;
        for (int e = tid; e < 4096; e += 512) {
            int kp = e >> 7, n = e & 127;
            int k0 = kp * 2;
            float x0 = __bfloat162float(xb[(size_t)k0 * TS_ + n]);
            float x1 = __bfloat162float(xb[(size_t)(k0 + 1) * TS_ + n]);
            *(uint32_t*)&Xt[n * 72 + k0] =
                packbf(lk(fmaf(x0, s_c[k0], s_c[64 + k0])),
                       lk(fmaf(x1, s_c[k0 + 1], s_c[64 + k0 + 1])));
        }
    }
    __syncthreads();

    const int mg = wid >> 2, ng = wid & 3;
    const int g = lane >> 2, tg = lane & 3;
    const uint32_t ws_b = smem_u32(Ws), xt_b = smem_u32(Xt);
    const uint32_t aAddr = ws_b +
        (uint32_t)((mg * 48 + (lane & 15)) * 72 + (lane >> 4) * 8) * 2;
    const int nsub = (lane & 7) + ((lane >> 4) & 1) * 8;
    const int koff = ((lane >> 3) & 1) * 8;
    const uint32_t bAddrBase = (uint32_t)((ng * 32 + nsub) * 72 + koff) * 2;

    uint32_t Af[3][4][4];
#pragma unroll
    for (int kk = 0; kk < 4; kk++) {
        ldsm_x4(Af[0][kk], aAddr + (uint32_t)kk * 32);
        ldsm_x4(Af[1][kk], aAddr + 16 * 72 * 2 + (uint32_t)kk * 32);
        ldsm_x4(Af[2][kk], aAddr + 32 * 72 * 2 + (uint32_t)kk * 32);
    }

    float bb[3][2];
#pragma unroll
    for (int mt = 0; mt < 3; mt++) {
        const int co = mg * 48 + mt * 16 + g;
        bb[mt][0] = __ldg(&bias[co]);
        bb[mt][1] = __ldg(&bias[co + 8]);
    }

    for (int ti = 0; ti < 18; ti++) {
        const int j0 = (group * 18 + ti) * 128;
        const uint32_t xtb = xt_b + (uint32_t)(ti & 1) * (128 * 72 * 2);
        if (ti < 17) {
            __nv_bfloat16* XtN = Xt + ((ti + 1) & 1) * (128 * 72);
            const __nv_bfloat16* xb = xbase + j0 + 128;
            for (int e = tid; e < 4096; e += 512) {
                int kp = e >> 7, n = e & 127;
                int k0 = kp * 2;
                float x0 = __bfloat162float(xb[(size_t)k0 * TS_ + n]);
                float x1 = __bfloat162float(xb[(size_t)(k0 + 1) * TS_ + n]);
                *(uint32_t*)&XtN[n * 72 + k0] =
                    packbf(lk(fmaf(x0, s_c[k0], s_c[64 + k0])),
                           lk(fmaf(x1, s_c[k0 + 1], s_c[64 + k0 + 1])));
            }
        }

        float acc[3][4][4];
#pragma unroll
        for (int mt = 0; mt < 3; mt++)
#pragma unroll
            for (int nt = 0; nt < 4; nt++)
#pragma unroll
                for (int i = 0; i < 4; i++) acc[mt][nt][i] = 0.f;

#pragma unroll
        for (int kk = 0; kk < 4; kk++) {
            const uint32_t ko2 = (uint32_t)kk * 32;
            uint32_t Bf0[4], Bf1[4];
            ldsm_x4(Bf0, xtb + bAddrBase + ko2);
            ldsm_x4(Bf1, xtb + bAddrBase + 16 * 72 * 2 + ko2);
            mma_bf16(acc[0][0], Af[0][kk][0], Af[0][kk][1], Af[0][kk][2], Af[0][kk][3], Bf0[0], Bf0[1]);
            mma_bf16(acc[1][0], Af[1][kk][0], Af[1][kk][1], Af[1][kk][2], Af[1][kk][3], Bf0[0], Bf0[1]);
            mma_bf16(acc[2][0], Af[2][kk][0], Af[2][kk][1], Af[2][kk][2], Af[2][kk][3], Bf0[0], Bf0[1]);
            mma_bf16(acc[0][1], Af[0][kk][0], Af[0][kk][1], Af[0][kk][2], Af[0][kk][3], Bf0[2], Bf0[3]);
            mma_bf16(acc[1][1], Af[1][kk][0], Af[1][kk][1], Af[1][kk][2], Af[1][kk][3], Bf0[2], Bf0[3]);
            mma_bf16(acc[2][1], Af[2][kk][0], Af[2][kk][1], Af[2][kk][2], Af[2][kk][3], Bf0[2], Bf0[3]);
            mma_bf16(acc[0][2], Af[0][kk][0], Af[0][kk][1], Af[0][kk][2], Af[0][kk][3], Bf1[0], Bf1[1]);
            mma_bf16(acc[1][2], Af[1][kk][0], Af[1][kk][1], Af[1][kk][2], Af[1][kk][3], Bf1[0], Bf1[1]);
            mma_bf16(acc[2][2], Af[2][kk][0], Af[2][kk][1], Af[2][kk][2], Af[2][kk][3], Bf1[0], Bf1[1]);
            mma_bf16(acc[0][3], Af[0][kk][0], Af[0][kk][1], Af[0][kk][2], Af[0][kk][3], Bf1[2], Bf1[3]);
            mma_bf16(acc[1][3], Af[1][kk][0], Af[1][kk][1], Af[1][kk][2], Af[1][kk][3], Bf1[2], Bf1[3]);
            mma_bf16(acc[2][3], Af[2][kk][0], Af[2][kk][1], Af[2][kk][2], Af[2][kk][3], Bf1[2], Bf1[3]);
        }

        const int ncol = b * S_ + j0 + ng * 32 + tg * 2;
#pragma unroll
        for (int mt = 0; mt < 3; mt++) {
#pragma unroll
            for (int r = 0; r < 2; r++) {
                const int co = mg * 48 + mt * 16 + r * 8 + g;
                const int z = co >> 6, mo = co & 63;
                const float bvv = bb[mt][r];
                __nv_bfloat16* op = g_qkvh + (size_t)z * QSZ_ +
                                    (size_t)(t * 64 + mo) * N_ + ncol;
#pragma unroll
                for (int nt = 0; nt < 4; nt++) {
                    *(uint32_t*)&op[nt * 8] =
                        packbf(acc[mt][nt][r * 2] + bvv, acc[mt][nt][r * 2 + 1] + bvv);
                }
            }
        }
        __syncthreads();
    }
}

// ---------------- fused attention + out_proj (unchanged from R14) ----------------
#define OTP2 72
#define SM_WS_OFF (8 * 64 * OTP2 * 2)
#define SM_ATTN_TOT (SM_WS_OFF + 64 * 72 * 2)

__global__ void __launch_bounds__(256, 2)
k_attn_fused(const float* __restrict__ bias, const float* __restrict__ bn0g,
             const float* __restrict__ bn0b) {
    extern __shared__ char smem[];
    __nv_bfloat16* Ot = (__nv_bfloat16*)smem;
    __nv_bfloat16* Ws = (__nv_bfloat16*)(smem + SM_WS_OFF);
    __shared__ float s_st[128];
    __shared__ float s_c0[128];
    const int tid = threadIdx.x, lane = tid & 31, wid = tid >> 5;
    const int j0 = blockIdx.x * 64;
    const int b = j0 / S_;
    const int jb = j0 - b * S_;

    if (tid < 128) s_st[tid] = 0.f;
    if (tid >= 128 && tid < 192) {
        const int c = tid - 128;
        const float inv = 1.0f / CNT_;
        float mu = g_sum0[c] * inv;
        float var = g_sum0[64 + c] * inv - mu * mu;
        float A = bn0g[c] * rsqrtf(var + 1e-5f);
        s_c0[c] = A;
        s_c0[64 + c] = bn0b[c] - mu * A;
    }
    {
        const uint4* src = (const uint4*)g_wout;
        for (int e = tid; e < 512; e += 256) {
            int co = e >> 3, q = e & 7;
            *(uint4*)&Ws[co * 72 + q * 8] = src[e];
        }
    }

    {
        const int nl = tid & 63;
        const int hp = tid >> 6;
        const int n = j0 + nl;
        const uint16_t* qp = (const uint16_t*)g_qkvh;
        const uint16_t* kp = (const uint16_t*)(g_qkvh + QSZ_);
        const uint16_t* vp = (const uint16_t*)(g_qkvh + 2 * (size_t)QSZ_);
        const float scale = 0.3535533905932738f;
        for (int i = 0; i < 2; i++) {
            const int cb = (hp * 2 + i) * 8;
            uint32_t kvp[8][4];
#pragma unroll
            for (int tt = 0; tt < 8; tt++)
#pragma unroll
                for (int j = 0; j < 4; j++) {
                    const size_t idx = (size_t)(tt * 64 + cb + 2 * j) * N_ + n;
                    uint32_t lo = kp[idx];
                    uint32_t hi = kp[idx + N_];
                    kvp[tt][j] = lo | (hi << 16);
                }
            float s[8][8];
#pragma unroll
            for (int tq = 0; tq < 8; tq++) {
                float q[8];
#pragma unroll
                for (int d = 0; d < 8; d++)
                    q[d] = __int_as_float((uint32_t)qp[(size_t)(tq * 64 + cb + d) * N_ + n] << 16) * scale;
                float mx = -1e30f;
#pragma unroll
                for (int tt = 0; tt < 8; tt++) {
                    float a = 0.f;
#pragma unroll
                    for (int j = 0; j < 4; j++) {
                        a = fmaf(q[2 * j], bflo(kvp[tt][j]), a);
                        a = fmaf(q[2 * j + 1], bfhi(kvp[tt][j]), a);
                    }
                    s[tq][tt] = a;
                    mx = fmaxf(mx, a);
                }
                float sum = 0.f;
#pragma unroll
                for (int tt = 0; tt < 8; tt++) { s[tq][tt] = fexp(s[tq][tt] - mx); sum += s[tq][tt]; }
                const float inv = 1.0f / sum;
#pragma unroll
                for (int tt = 0; tt < 8; tt++) s[tq][tt] *= inv;
            }
#pragma unroll
            for (int tt = 0; tt < 8; tt++)
#pragma unroll
                for (int j = 0; j < 4; j++) {
                    const size_t idx = (size_t)(tt * 64 + cb + 2 * j) * N_ + n;
                    uint32_t lo = vp[idx];
                    uint32_t hi = vp[idx + N_];
                    kvp[tt][j] = lo | (hi << 16);
                }
#pragma unroll
            for (int tq = 0; tq < 8; tq++) {
#pragma unroll
                for (int j = 0; j < 4; j++) {
                    float o0 = 0.f, o1 = 0.f;
#pragma unroll
                    for (int tt = 0; tt < 8; tt++) {
                        o0 = fmaf(s[tq][tt], bflo(kvp[tt][j]), o0);
                        o1 = fmaf(s[tq][tt], bfhi(kvp[tt][j]), o1);
                    }
                    Ot[(tq * 64 + cb + 2 * j) * OTP2 + nl] = __float2bfloat16(o0);
                    Ot[(tq * 64 + cb + 2 * j + 1) * OTP2 + nl] = __float2bfloat16(o1);
                }
            }
        }
    }
    __syncthreads();

    const int mg = wid >> 1, nh = wid & 1;
    const int g = lane >> 2, tg = lane & 3;
    const uint32_t ws_b = smem_u32(Ws);
    const uint32_t ot_b = smem_u32(Ot);
    const uint32_t aAddr0 = ws_b + (uint32_t)((mg * 16 + (lane & 15)) * 72 + (lane >> 4) * 8) * 2;
    const int krow_l = (lane & 7) + ((lane >> 3) & 1) * 8;
    const int np_l = nh * 32 + ((lane >> 4) & 1) * 8;

    uint32_t Af[4][4];
#pragma unroll
    for (int kk = 0; kk < 4; kk++)
        ldsm_x4(Af[kk], aAddr0 + (uint32_t)kk * 32);

    float ps[2], pq[2];
    ps[0] = ps[1] = pq[0] = pq[1] = 0.f;

    for (int t = 0; t < 8; t++) {
        float acc[4][4];
#pragma unroll
        for (int nt = 0; nt < 4; nt++)
#pragma unroll
            for (int i = 0; i < 4; i++) acc[nt][i] = 0.f;

#pragma unroll
        for (int kk = 0; kk < 4; kk++) {
            uint32_t Bf0[4], Bf1[4];
            const uint32_t base =
                ot_b + (uint32_t)((t * 64 + kk * 16 + krow_l) * OTP2 + np_l) * 2;
            ldsm_x4_t(Bf0, base);
            ldsm_x4_t(Bf1, base + 32);
            mma_bf16(acc[0], Af[kk][0], Af[kk][1], Af[kk][2], Af[kk][3], Bf0[0], Bf0[1]);
            mma_bf16(acc[1], Af[kk][0], Af[kk][1], Af[kk][2], Af[kk][3], Bf0[2], Bf0[3]);
            mma_bf16(acc[2], Af[kk][0], Af[kk][1], Af[kk][2], Af[kk][3], Bf1[0], Bf1[1]);
            mma_bf16(acc[3], Af[kk][0], Af[kk][1], Af[kk][2], Af[kk][3], Bf1[2], Bf1[3]);
        }

#pragma unroll
        for (int r = 0; r < 2; r++) {
            const int co = mg * 16 + r * 8 + g;
            const float bb = __ldg(&bias[co]);
            const float A0 = s_c0[co], B0 = s_c0[64 + co];
            const size_t rowb = ((size_t)(b * C_ + co) * T_ + t) * S_ + jb;
#pragma unroll
            for (int nt = 0; nt < 4; nt++) {
                const int px = nh * 32 + nt * 8 + tg * 2;
                uint32_t u = *(const uint32_t*)&g_xh[rowb + px];
                __nv_bfloat162 bp = *(__nv_bfloat162*)&u;
                float zx = lk(fmaf(__bfloat162float(bp.x), A0, B0)) + acc[nt][r * 2] + bb;
                float zy = lk(fmaf(__bfloat162float(bp.y), A0, B0)) + acc[nt][r * 2 + 1] + bb;
                *(uint32_t*)&g_zh[rowb + px] = packbf(zx, zy);
                ps[r] += zx + zy;
                pq[r] += zx * zx + zy * zy;
            }
        }
    }

#pragma unroll
    for (int r = 0; r < 2; r++) {
        ps[r] += __shfl_xor_sync(0xffffffffu, ps[r], 1);
        ps[r] += __shfl_xor_sync(0xffffffffu, ps[r], 2);
        pq[r] += __shfl_xor_sync(0xffffffffu, pq[r], 1);
        pq[r] += __shfl_xor_sync(0xffffffffu, pq[r], 2);
    }
    if ((lane & 3) == 0) {
#pragma unroll
        for (int r = 0; r < 2; r++) {
            const int co = mg * 16 + r * 8 + g;
            atomicAdd(&s_st[co], ps[r]);
            atomicAdd(&s_st[64 + co], pq[r]);
        }
    }
    __syncthreads();
    if (tid < 128) atomicAdd(&g_sum1[tid], s_st[tid]);
}

// ---------------- spatial mean of leaky(bn1(z)), coef1 inline ----------------
__global__ void __launch_bounds__(256) k_mean(const float* __restrict__ bn1g,
                                              const float* __restrict__ bn1b) {
    const int bid = blockIdx.x;
    const int c = (bid >> 3) & 63;
    const float inv = 1.0f / CNT_;
    const float mu = g_sum1[c] * inv;
    const float var = g_sum1[64 + c] * inv - mu * mu;
    const float A = bn1g[c] * rsqrtf(var + 1e-5f);
    const float Bv = bn1b[c] - mu * A;
    const uint32_t* p = (const uint32_t*)(g_zh + (size_t)bid * S_);
    float s = 0.f;
    for (int i = threadIdx.x; i < S_ / 2; i += 256) {
        uint32_t u = p[i];
        __nv_bfloat162 bp = *(__nv_bfloat162*)&u;
        s += lk(fmaf(__bfloat162float(bp.x), A, Bv));
        s += lk(fmaf(__bfloat162float(bp.y), A, Bv));
    }
#pragma unroll
    for (int off = 16; off; off >>= 1) s += __shfl_down_sync(0xffffffffu, s, off);
    __shared__ float wa[8];
    const int lane = threadIdx.x & 31, wid = threadIdx.x >> 5;
    if (lane == 0) wa[wid] = s;
    __syncthreads();
    if (threadIdx.x == 0) {
        float ts = 0.f;
#pragma unroll
        for (int i = 0; i < 8; i++) ts += wa[i];
        g_m[bid] = ts * (1.0f / (float)S_);
    }
}

// ---------------- dynamic depthwise 5x5 conv (kernel-gen fused) ----------------
__global__ void __launch_bounds__(256) k_dynconv(const float* __restrict__ h,
                                                 const float* __restrict__ w1,
                                                 const float* __restrict__ b1,
                                                 float* __restrict__ out) {
    __shared__ float sp[100 * 100];
    __shared__ float sk[25];
    const int bid = blockIdx.x;
    const int b = bid >> 9;
    const int t = bid & 7;
    const int tid = threadIdx.x;
    const float* base = h + (size_t)bid * S_;

    for (int i = tid; i < 10000; i += 256) sp[i] = 0.f;
    if (tid < 25) {
        float a = __ldg(&b1[tid]);
#pragma unroll 8
        for (int c = 0; c < 64; c++)
            a = fmaf(g_m[(b * C_ + c) * T_ + t], __ldg(&w1[tid * 64 + c]), a);
        sk[tid] = a;
    }
    __syncthreads();
    for (int i = tid; i < S_; i += 256) {
        const int r = i / 96, col = i - r * 96;
        sp[(r + 2) * 100 + col + 2] = base[i];
    }
    __syncthreads();

    float kr[25];
#pragma unroll
    for (int q = 0; q < 25; q++) kr[q] = sk[q];

    float* ob = out + (size_t)bid * S_;
    for (int i = tid; i < S_; i += 256) {
        const int r = i / 96, col = i - r * 96;
        const float* pp = &sp[r * 100 + col];
        float a = 0.f;
#pragma unroll
        for (int ii = 0; ii < 5; ii++)
#pragma unroll
            for (int jj = 0; jj < 5; jj++)
                a = fmaf(pp[ii * 100 + jj], kr[ii * 5 + jj], a);
        ob[i] = a;
    }
}

// ---------------- launch ----------------
extern "C" void kernel_launch(void* const* d_in, const int* in_sizes, int n_in,
                              void* d_out, int out_size) {
    const float* h       = (const float*)d_in[0];
    const float* conv0_w = (const float*)d_in[1];
    const float* conv0_b = (const float*)d_in[2];
    const float* bn0_g   = (const float*)d_in[3];
    const float* bn0_b   = (const float*)d_in[4];
    const float* bn1_g   = (const float*)d_in[5];
    const float* bn1_b   = (const float*)d_in[6];
    const float* inW     = (const float*)d_in[7];
    const float* inB     = (const float*)d_in[8];
    const float* outW    = (const float*)d_in[9];
    const float* outB    = (const float*)d_in[10];
    const float* c1w     = (const float*)d_in[11];
    const float* c1b     = (const float*)d_in[12];
    float* out = (float*)d_out;

    cudaFuncSetAttribute(k_conv0_mma, cudaFuncAttributeMaxDynamicSharedMemorySize,
                         SM_CONV_TOT);
    cudaFuncSetAttribute(k_qkv_mma, cudaFuncAttributeMaxDynamicSharedMemorySize,
                         QSM_TOT);
    cudaFuncSetAttribute(k_attn_fused, cudaFuncAttributeMaxDynamicSharedMemorySize,
                         SM_ATTN_TOT);

    k_prep<<<144, 256>>>(conv0_w, inW, outW);
    k_conv0_mma<<<dim3(4, B_ * T_), 512, SM_CONV_TOT>>>(h, conv0_b);
    k_qkv_mma<<<dim3(4, B_ * T_), 512, QSM_TOT>>>(inB, bn0_g, bn0_b);
    k_attn_fused<<<N_ / 64, 256, SM_ATTN_TOT>>>(outB, bn0_g, bn0_b);
    k_mean<<<B_ * C_ * T_, 256>>>(bn1_g, bn1_b);
    k_dynconv<<<B_ * C_ * T_, 256>>>(h, c1w, c1b, out);
}

// round 16
// speedup vs baseline: 1.0190x; 1.0190x over previous
#include <cuda_runtime.h>
#include <cuda_bf16.h>
#include <cstdint>

// Problem constants
#define B_ 4
#define C_ 64
#define T_ 8
#define X_ 96
#define Y_ 96
#define S_ 9216            // X_*Y_
#define N_ 36864           // B_*S_
#define TS_ 73728          // T_*S_
#define TOTAL_ 18874368    // B_*C_*T_*S_
#define QSZ_ 18874368      // T_*C_*N_
#define CNT_ 294912.0f     // B_*T_*S_

// -------- scratch (device globals; no runtime allocation) --------
__device__ __nv_bfloat16 g_xh[TOTAL_];            // conv0 raw output (pre-BN0), bf16
__device__ __nv_bfloat16 g_qkvh[3 * QSZ_];        // q,k,v bf16, [z][t][c][n]
__device__ __nv_bfloat16 g_zh[TOTAL_];            // residual + out_proj (pre-BN1), bf16
__device__ float g_sum0[128];
__device__ float g_sum1[128];
__device__ float g_m[B_ * C_ * T_];
__device__ __align__(16) __nv_bfloat16 g_wk[64 * 576];   // conv0 [co][k], k=tap*64+ci
__device__ __align__(16) __nv_bfloat16 g_wqkv[192 * 64]; // in_proj bf16
__device__ __align__(16) __nv_bfloat16 g_wout[64 * 64];  // out_proj bf16

__device__ __forceinline__ float lk(float v) { return v >= 0.f ? v : 0.01f * v; }

// FFMA-only exp
__device__ __forceinline__ float fexp(float x) {
    const float L2E = 1.4426950408889634f;
    float t = fmaf(x, L2E, 12582912.0f);
    int ii = __float_as_int(t) - 0x4B400000;
    float i = t - 12582912.0f;
    float f = fmaf(x, L2E, -i);
    float p = 1.3333558146e-3f;
    p = fmaf(p, f, 9.6181291918e-3f);
    p = fmaf(p, f, 5.5504108664e-2f);
    p = fmaf(p, f, 2.4022650695e-1f);
    p = fmaf(p, f, 6.9314718056e-1f);
    p = fmaf(p, f, 1.0f);
    return __int_as_float(__float_as_int(p) + (ii << 23));
}

__device__ __forceinline__ float bflo(uint32_t u) { return __int_as_float(u << 16); }
__device__ __forceinline__ float bfhi(uint32_t u) { return __int_as_float(u & 0xFFFF0000u); }

__device__ __forceinline__ void mma_bf16(float* c, uint32_t a0, uint32_t a1,
                                         uint32_t a2, uint32_t a3,
                                         uint32_t b0, uint32_t b1) {
    asm volatile(
        "mma.sync.aligned.m16n8k16.row.col.f32.bf16.bf16.f32 "
        "{%0,%1,%2,%3}, {%4,%5,%6,%7}, {%8,%9}, {%0,%1,%2,%3};"
        : "+f"(c[0]), "+f"(c[1]), "+f"(c[2]), "+f"(c[3])
        : "r"(a0), "r"(a1), "r"(a2), "r"(a3), "r"(b0), "r"(b1));
}

__device__ __forceinline__ uint32_t packbf(float a, float b) {
    __nv_bfloat162 p = __floats2bfloat162_rn(a, b);
    return *(uint32_t*)&p;
}

__device__ __forceinline__ uint32_t smem_u32(const void* p) {
    uint32_t a;
    asm("{ .reg .u64 t; cvta.to.shared.u64 t, %1; cvt.u32.u64 %0, t; }" : "=r"(a) : "l"(p));
    return a;
}

__device__ __forceinline__ void ldsm_x4(uint32_t* r, uint32_t addr) {
    asm volatile("ldmatrix.sync.aligned.m8n8.x4.shared.b16 {%0,%1,%2,%3}, [%4];"
        : "=r"(r[0]), "=r"(r[1]), "=r"(r[2]), "=r"(r[3]) : "r"(addr));
}
__device__ __forceinline__ void ldsm_x4_t(uint32_t* r, uint32_t addr) {
    asm volatile("ldmatrix.sync.aligned.m8n8.x4.trans.shared.b16 {%0,%1,%2,%3}, [%4];"
        : "=r"(r[0]), "=r"(r[1]), "=r"(r[2]), "=r"(r[3]) : "r"(addr));
}

// ===================== combined prep =====================
__global__ void k_prep(const float* __restrict__ w, const float* __restrict__ inW,
                       const float* __restrict__ outW) {
    int i = blockIdx.x * 256 + threadIdx.x;
    if (i < 128) { g_sum0[i] = 0.f; g_sum1[i] = 0.f; }
    if (i < 64 * 576) {
        int co = i / 576, k = i - co * 576;
        g_wk[i] = __float2bfloat16(w[(co * 64 + (k & 63)) * 9 + (k >> 6)]);
    }
    if (i < 192 * 64) g_wqkv[i] = __float2bfloat16(inW[i]);
    if (i < 64 * 64) g_wout[i] = __float2bfloat16(outW[i]);
}

// ===================== conv0: persistent bf16 mma + ldmatrix (R14 form) ==========
#define SINW 72
#define ROWE (98 * SINW)
#define RING 8
#define WKS 584
#define SM_WK_OFF (RING * ROWE * 2)
#define SM_CONV_TOT (SM_WK_OFF + 64 * WKS * 2)

__device__ __forceinline__ void stage_row(__nv_bfloat16* sin_s, const float* hb,
                                          int gx, int tid) {
    const int slot = (gx + 8) & 7;
    __nv_bfloat16* dst = sin_s + slot * ROWE;
    if ((unsigned)gx >= 96u) {
        for (int e = tid; e < 6144; e += 512) {
            int ci = e / 96, y = e - ci * 96;
            dst[(y + 1) * SINW + ci] = __float2bfloat16(0.f);
        }
    } else {
        const float* hp = hb + (size_t)gx * 96;
        for (int e = tid; e < 6144; e += 512) {
            int ci = e / 96, y = e - ci * 96;
            dst[(y + 1) * SINW + ci] = __float2bfloat16(hp[(size_t)ci * TS_ + y]);
        }
    }
    if (tid < 64) dst[tid] = __float2bfloat16(0.f);
    else if (tid < 128) dst[97 * SINW + (tid - 64)] = __float2bfloat16(0.f);
}

__global__ void __launch_bounds__(512)
k_conv0_mma(const float* __restrict__ h, const float* __restrict__ bias) {
    extern __shared__ char smem[];
    __nv_bfloat16* sin_s = (__nv_bfloat16*)smem;
    __nv_bfloat16* wk_s = (__nv_bfloat16*)(smem + SM_WK_OFF);
    __shared__ float s_st[128];

    const int tid = threadIdx.x, lane = tid & 31, wid = tid >> 5;
    const int group = blockIdx.x, bt = blockIdx.y, b = bt >> 3, t = bt & 7;
    const float* hb = h + (size_t)b * (64 * TS_) + (size_t)t * S_;

    if (tid < 128) s_st[tid] = 0.f;
    {
        const uint4* src = (const uint4*)g_wk;
        for (int e = tid; e < 4608; e += 512) {
            int co = e / 72, q = e - co * 72;
            *(uint4*)&wk_s[co * WKS + q * 8] = src[e];
        }
    }
    {
        const int p0 = group * 2304;
        const int xlo = p0 / 96, xhi = (p0 + 255) / 96;
        for (int gx = xlo - 1; gx <= xhi + 1; gx++) stage_row(sin_s, hb, gx, tid);
    }
    __syncthreads();

    const int mg = wid >> 1, nh = wid & 1;
    const int g = lane >> 2, tg = lane & 3;

    const uint32_t sin_b = smem_u32(sin_s);
    const uint32_t wk_b = smem_u32(wk_s);

    uint32_t wkaddr[2];
    {
        const int koff = ((lane >> 3) & 1) * 8;
        const int cosub = (lane & 7) + ((lane >> 4) & 1) * 8;
#pragma unroll
        for (int ntp = 0; ntp < 2; ntp++) {
            const int co = nh * 32 + ntp * 16 + cosub;
            wkaddr[ntp] = wk_b + (uint32_t)(co * WKS + koff) * 2;
        }
    }
    const uint32_t khiA = (uint32_t)((lane >> 4) * 16);

    float bv[4][2];
#pragma unroll
    for (int nt = 0; nt < 4; nt++) {
        const int co0 = nh * 32 + nt * 8 + tg * 2;
        bv[nt][0] = __ldg(&bias[co0]);
        bv[nt][1] = __ldg(&bias[co0 + 1]);
    }

    float st_s[8], st_q[8];
#pragma unroll
    for (int i = 0; i < 8; i++) { st_s[i] = 0.f; st_q[i] = 0.f; }

    __nv_bfloat16* obB = g_xh + (size_t)b * (64 * TS_) + (size_t)t * S_;

    for (int ti = 0; ti < 9; ti++) {
        const int p0 = group * 2304 + ti * 256;
        const int xhi = (p0 + 255) / 96;
        if (ti < 8) {
            const int xhin = (p0 + 511) / 96;
            for (int gx = xhi + 2; gx <= xhin + 1; gx++) stage_row(sin_s, hb, gx, tid);
        }

        uint32_t aRB[2][3];
        {
            const int plbase = p0 + mg * 32 + (lane & 15);
#pragma unroll
            for (int mt = 0; mt < 2; mt++) {
                const int pl = plbase + mt * 16;
                const int px = pl / 96, py = pl - px * 96;
#pragma unroll
                for (int dx = 0; dx < 3; dx++)
                    aRB[mt][dx] = sin_b +
                        (uint32_t)(((px + dx + 7) & 7) * ROWE + py * SINW) * 2 + khiA;
            }
        }

        float acc[2][4][4];
#pragma unroll
        for (int mt = 0; mt < 2; mt++)
#pragma unroll
            for (int nt = 0; nt < 4; nt++)
#pragma unroll
                for (int i = 0; i < 4; i++) acc[mt][nt][i] = 0.f;

#pragma unroll
        for (int tap = 0; tap < 9; tap++) {
            const int dx = tap / 3, dy = tap - dx * 3;
            const uint32_t dyoff = (uint32_t)(dy * SINW) * 2;
#pragma unroll
            for (int kk = 0; kk < 4; kk++) {
                const uint32_t ko2 = (uint32_t)kk * 32;
                uint32_t A0[4], A1[4], Bf0[4], Bf1[4];
                ldsm_x4(A0, aRB[0][dx] + dyoff + ko2);
                ldsm_x4(A1, aRB[1][dx] + dyoff + ko2);
                const uint32_t bk = (uint32_t)(tap * 64 + kk * 16) * 2;
                ldsm_x4(Bf0, wkaddr[0] + bk);
                ldsm_x4(Bf1, wkaddr[1] + bk);
                mma_bf16(acc[0][0], A0[0], A0[1], A0[2], A0[3], Bf0[0], Bf0[1]);
                mma_bf16(acc[1][0], A1[0], A1[1], A1[2], A1[3], Bf0[0], Bf0[1]);
                mma_bf16(acc[0][1], A0[0], A0[1], A0[2], A0[3], Bf0[2], Bf0[3]);
                mma_bf16(acc[1][1], A1[0], A1[1], A1[2], A1[3], Bf0[2], Bf0[3]);
                mma_bf16(acc[0][2], A0[0], A0[1], A0[2], A0[3], Bf1[0], Bf1[1]);
                mma_bf16(acc[1][2], A1[0], A1[1], A1[2], A1[3], Bf1[0], Bf1[1]);
                mma_bf16(acc[0][3], A0[0], A0[1], A0[2], A0[3], Bf1[2], Bf1[3]);
                mma_bf16(acc[1][3], A1[0], A1[1], A1[2], A1[3], Bf1[2], Bf1[3]);
            }
        }

        __nv_bfloat16* ob = obB + p0;
#pragma unroll
        for (int nt = 0; nt < 4; nt++) {
            const int co0 = nh * 32 + nt * 8 + tg * 2;
#pragma unroll
            for (int mt = 0; mt < 2; mt++) {
                const int pr = mg * 32 + mt * 16 + g;
                float v0 = acc[mt][nt][0] + bv[nt][0];
                float v1 = acc[mt][nt][1] + bv[nt][1];
                float v2 = acc[mt][nt][2] + bv[nt][0];
                float v3 = acc[mt][nt][3] + bv[nt][1];
                ob[(size_t)co0 * TS_ + pr]           = __float2bfloat16(v0);
                ob[(size_t)(co0 + 1) * TS_ + pr]     = __float2bfloat16(v1);
                ob[(size_t)co0 * TS_ + pr + 8]       = __float2bfloat16(v2);
                ob[(size_t)(co0 + 1) * TS_ + pr + 8] = __float2bfloat16(v3);
                st_s[nt * 2]     += v0 + v2;
                st_q[nt * 2]     += v0 * v0 + v2 * v2;
                st_s[nt * 2 + 1] += v1 + v3;
                st_q[nt * 2 + 1] += v1 * v1 + v3 * v3;
            }
        }
        __syncthreads();
    }

#pragma unroll
    for (int i = 0; i < 8; i++) {
        st_s[i] += __shfl_xor_sync(0xffffffffu, st_s[i], 4);
        st_s[i] += __shfl_xor_sync(0xffffffffu, st_s[i], 8);
        st_s[i] += __shfl_xor_sync(0xffffffffu, st_s[i], 16);
        st_q[i] += __shfl_xor_sync(0xffffffffu, st_q[i], 4);
        st_q[i] += __shfl_xor_sync(0xffffffffu, st_q[i], 8);
        st_q[i] += __shfl_xor_sync(0xffffffffu, st_q[i], 16);
    }
    if (lane < 4) {
#pragma unroll
        for (int nt = 0; nt < 4; nt++)
#pragma unroll
            for (int r = 0; r < 2; r++) {
                const int co = nh * 32 + nt * 8 + lane * 2 + r;
                atomicAdd(&s_st[co], st_s[nt * 2 + r]);
                atomicAdd(&s_st[64 + co], st_q[nt * 2 + r]);
            }
    }
    __syncthreads();
    if (tid < 128) atomicAdd(&g_sum0[tid], s_st[tid]);
}

// ---------------- qkv (unchanged) ----------------
#define QSM_WS (2 * 128 * 72 * 2)
#define QSM_TOT (QSM_WS + 192 * 72 * 2)

__global__ void __launch_bounds__(512) k_qkv_mma(const float* __restrict__ bias,
                                                 const float* __restrict__ bn0g,
                                                 const float* __restrict__ bn0b) {
    extern __shared__ char smem[];
    __nv_bfloat16* Xt = (__nv_bfloat16*)smem;
    __nv_bfloat16* Ws = (__nv_bfloat16*)(smem + QSM_WS);
    __shared__ float s_c[128];
    const int tid = threadIdx.x, lane = tid & 31, wid = tid >> 5;
    const int group = blockIdx.x;
    const int bt = blockIdx.y, b = bt >> 3, t = bt & 7;

    if (tid < 64) {
        const float inv = 1.0f / CNT_;
        float mu = g_sum0[tid] * inv;
        float var = g_sum0[64 + tid] * inv - mu * mu;
        float A = bn0g[tid] * rsqrtf(var + 1e-5f);
        s_c[tid] = A;
        s_c[64 + tid] = bn0b[tid] - mu * A;
    }
    {
        const uint4* src = (const uint4*)g_wqkv;
        for (int e = tid; e < 1536; e += 512) {
            int co = e >> 3, q = e & 7;
            *(uint4*)&Ws[co * 72 + q * 8] = src[e];
        }
    }
    __syncthreads();

    const __nv_bfloat16* xbase = g_xh + ((size_t)(b * C_) * T_ + t) * S_;
    {
        const __nv_bfloat16* xb = xbase + group * 18 * 128;
        for (int e = tid; e < 4096; e += 512) {
            int kp = e >> 7, n = e & 127;
            int k0 = kp * 2;
            float x0 = __bfloat162float(xb[(size_t)k0 * TS_ + n]);
            float x1 = __bfloat162float(xb[(size_t)(k0 + 1) * TS_ + n]);
            *(uint32_t*)&Xt[n * 72 + k0] =
                packbf(lk(fmaf(x0, s_c[k0], s_c[64 + k0])),
                       lk(fmaf(x1, s_c[k0 + 1], s_c[64 + k0 + 1])));
        }
    }
    __syncthreads();

    const int mg = wid >> 2, ng = wid & 3;
    const int g = lane >> 2, tg = lane & 3;
    const uint32_t ws_b = smem_u32(Ws), xt_b = smem_u32(Xt);
    const uint32_t aAddr = ws_b +
        (uint32_t)((mg * 48 + (lane & 15)) * 72 + (lane >> 4) * 8) * 2;
    const int nsub = (lane & 7) + ((lane >> 4) & 1) * 8;
    const int koff = ((lane >> 3) & 1) * 8;
    const uint32_t bAddrBase = (uint32_t)((ng * 32 + nsub) * 72 + koff) * 2;

    uint32_t Af[3][4][4];
#pragma unroll
    for (int kk = 0; kk < 4; kk++) {
        ldsm_x4(Af[0][kk], aAddr + (uint32_t)kk * 32);
        ldsm_x4(Af[1][kk], aAddr + 16 * 72 * 2 + (uint32_t)kk * 32);
        ldsm_x4(Af[2][kk], aAddr + 32 * 72 * 2 + (uint32_t)kk * 32);
    }

    float bb[3][2];
#pragma unroll
    for (int mt = 0; mt < 3; mt++) {
        const int co = mg * 48 + mt * 16 + g;
        bb[mt][0] = __ldg(&bias[co]);
        bb[mt][1] = __ldg(&bias[co + 8]);
    }

    for (int ti = 0; ti < 18; ti++) {
        const int j0 = (group * 18 + ti) * 128;
        const uint32_t xtb = xt_b + (uint32_t)(ti & 1) * (128 * 72 * 2);
        if (ti < 17) {
            __nv_bfloat16* XtN = Xt + ((ti + 1) & 1) * (128 * 72);
            const __nv_bfloat16* xb = xbase + j0 + 128;
            for (int e = tid; e < 4096; e += 512) {
                int kp = e >> 7, n = e & 127;
                int k0 = kp * 2;
                float x0 = __bfloat162float(xb[(size_t)k0 * TS_ + n]);
                float x1 = __bfloat162float(xb[(size_t)(k0 + 1) * TS_ + n]);
                *(uint32_t*)&XtN[n * 72 + k0] =
                    packbf(lk(fmaf(x0, s_c[k0], s_c[64 + k0])),
                           lk(fmaf(x1, s_c[k0 + 1], s_c[64 + k0 + 1])));
            }
        }

        float acc[3][4][4];
#pragma unroll
        for (int mt = 0; mt < 3; mt++)
#pragma unroll
            for (int nt = 0; nt < 4; nt++)
#pragma unroll
                for (int i = 0; i < 4; i++) acc[mt][nt][i] = 0.f;

#pragma unroll
        for (int kk = 0; kk < 4; kk++) {
            const uint32_t ko2 = (uint32_t)kk * 32;
            uint32_t Bf0[4], Bf1[4];
            ldsm_x4(Bf0, xtb + bAddrBase + ko2);
            ldsm_x4(Bf1, xtb + bAddrBase + 16 * 72 * 2 + ko2);
            mma_bf16(acc[0][0], Af[0][kk][0], Af[0][kk][1], Af[0][kk][2], Af[0][kk][3], Bf0[0], Bf0[1]);
            mma_bf16(acc[1][0], Af[1][kk][0], Af[1][kk][1], Af[1][kk][2], Af[1][kk][3], Bf0[0], Bf0[1]);
            mma_bf16(acc[2][0], Af[2][kk][0], Af[2][kk][1], Af[2][kk][2], Af[2][kk][3], Bf0[0], Bf0[1]);
            mma_bf16(acc[0][1], Af[0][kk][0], Af[0][kk][1], Af[0][kk][2], Af[0][kk][3], Bf0[2], Bf0[3]);
            mma_bf16(acc[1][1], Af[1][kk][0], Af[1][kk][1], Af[1][kk][2], Af[1][kk][3], Bf0[2], Bf0[3]);
            mma_bf16(acc[2][1], Af[2][kk][0], Af[2][kk][1], Af[2][kk][2], Af[2][kk][3], Bf0[2], Bf0[3]);
            mma_bf16(acc[0][2], Af[0][kk][0], Af[0][kk][1], Af[0][kk][2], Af[0][kk][3], Bf1[0], Bf1[1]);
            mma_bf16(acc[1][2], Af[1][kk][0], Af[1][kk][1], Af[1][kk][2], Af[1][kk][3], Bf1[0], Bf1[1]);
            mma_bf16(acc[2][2], Af[2][kk][0], Af[2][kk][1], Af[2][kk][2], Af[2][kk][3], Bf1[0], Bf1[1]);
            mma_bf16(acc[0][3], Af[0][kk][0], Af[0][kk][1], Af[0][kk][2], Af[0][kk][3], Bf1[2], Bf1[3]);
            mma_bf16(acc[1][3], Af[1][kk][0], Af[1][kk][1], Af[1][kk][2], Af[1][kk][3], Bf1[2], Bf1[3]);
            mma_bf16(acc[2][3], Af[2][kk][0], Af[2][kk][1], Af[2][kk][2], Af[2][kk][3], Bf1[2], Bf1[3]);
        }

        const int ncol = b * S_ + j0 + ng * 32 + tg * 2;
#pragma unroll
        for (int mt = 0; mt < 3; mt++) {
#pragma unroll
            for (int r = 0; r < 2; r++) {
                const int co = mg * 48 + mt * 16 + r * 8 + g;
                const int z = co >> 6, mo = co & 63;
                const float bvv = bb[mt][r];
                __nv_bfloat16* op = g_qkvh + (size_t)z * QSZ_ +
                                    (size_t)(t * 64 + mo) * N_ + ncol;
#pragma unroll
                for (int nt = 0; nt < 4; nt++) {
                    *(uint32_t*)&op[nt * 8] =
                        packbf(acc[mt][nt][r * 2] + bvv, acc[mt][nt][r * 2 + 1] + bvv);
                }
            }
        }
        __syncthreads();
    }
}

// ---------------- fused attention + out_proj (v-loads hidden under softmax) ----------
#define OTP2 72
#define SM_WS_OFF (8 * 64 * OTP2 * 2)
#define SM_ATTN_TOT (SM_WS_OFF + 64 * 72 * 2)

__global__ void __launch_bounds__(256, 2)
k_attn_fused(const float* __restrict__ bias, const float* __restrict__ bn0g,
             const float* __restrict__ bn0b) {
    extern __shared__ char smem[];
    __nv_bfloat16* Ot = (__nv_bfloat16*)smem;
    __nv_bfloat16* Ws = (__nv_bfloat16*)(smem + SM_WS_OFF);
    __shared__ float s_st[128];
    __shared__ float s_c0[128];
    const int tid = threadIdx.x, lane = tid & 31, wid = tid >> 5;
    const int j0 = blockIdx.x * 64;
    const int b = j0 / S_;
    const int jb = j0 - b * S_;

    if (tid < 128) s_st[tid] = 0.f;
    if (tid >= 128 && tid < 192) {
        const int c = tid - 128;
        const float inv = 1.0f / CNT_;
        float mu = g_sum0[c] * inv;
        float var = g_sum0[64 + c] * inv - mu * mu;
        float A = bn0g[c] * rsqrtf(var + 1e-5f);
        s_c0[c] = A;
        s_c0[64 + c] = bn0b[c] - mu * A;
    }
    {
        const uint4* src = (const uint4*)g_wout;
        for (int e = tid; e < 512; e += 256) {
            int co = e >> 3, q = e & 7;
            *(uint4*)&Ws[co * 72 + q * 8] = src[e];
        }
    }

    // ---- phase 1: attention, 64 n x 8 heads; thread = (n, 2 heads) ----
    {
        const int nl = tid & 63;
        const int hp = tid >> 6;
        const int n = j0 + nl;
        const uint16_t* qp = (const uint16_t*)g_qkvh;
        const uint16_t* kp = (const uint16_t*)(g_qkvh + QSZ_);
        const uint16_t* vp = (const uint16_t*)(g_qkvh + 2 * (size_t)QSZ_);
        const float scale = 0.3535533905932738f;
        for (int i = 0; i < 2; i++) {
            const int cb = (hp * 2 + i) * 8;
            uint32_t kvp[8][4];
#pragma unroll
            for (int tt = 0; tt < 8; tt++)
#pragma unroll
                for (int j = 0; j < 4; j++) {
                    const size_t idx = (size_t)(tt * 64 + cb + 2 * j) * N_ + n;
                    uint32_t lo = kp[idx];
                    uint32_t hi = kp[idx + N_];
                    kvp[tt][j] = lo | (hi << 16);
                }
            // --- all dot products first (k dies after this) ---
            float s[8][8], mx[8];
#pragma unroll
            for (int tq = 0; tq < 8; tq++) {
                float q[8];
#pragma unroll
                for (int d = 0; d < 8; d++)
                    q[d] = __int_as_float((uint32_t)qp[(size_t)(tq * 64 + cb + d) * N_ + n] << 16) * scale;
                float m = -1e30f;
#pragma unroll
                for (int tt = 0; tt < 8; tt++) {
                    float a = 0.f;
#pragma unroll
                    for (int j = 0; j < 4; j++) {
                        a = fmaf(q[2 * j], bflo(kvp[tt][j]), a);
                        a = fmaf(q[2 * j + 1], bfhi(kvp[tt][j]), a);
                    }
                    s[tq][tt] = a;
                    m = fmaxf(m, a);
                }
                mx[tq] = m;
            }
            // --- issue v loads NOW (independent); softmax below hides their latency ---
#pragma unroll
            for (int tt = 0; tt < 8; tt++)
#pragma unroll
                for (int j = 0; j < 4; j++) {
                    const size_t idx = (size_t)(tt * 64 + cb + 2 * j) * N_ + n;
                    uint32_t lo = vp[idx];
                    uint32_t hi = vp[idx + N_];
                    kvp[tt][j] = lo | (hi << 16);
                }
            // --- softmax (~500 cyc of FFMA chains, covers v-load latency) ---
#pragma unroll
            for (int tq = 0; tq < 8; tq++) {
                float sum = 0.f;
#pragma unroll
                for (int tt = 0; tt < 8; tt++) { s[tq][tt] = fexp(s[tq][tt] - mx[tq]); sum += s[tq][tt]; }
                const float inv = 1.0f / sum;
#pragma unroll
                for (int tt = 0; tt < 8; tt++) s[tq][tt] *= inv;
            }
            // --- o = s @ v ---
#pragma unroll
            for (int tq = 0; tq < 8; tq++) {
#pragma unroll
                for (int j = 0; j < 4; j++) {
                    float o0 = 0.f, o1 = 0.f;
#pragma unroll
                    for (int tt = 0; tt < 8; tt++) {
                        o0 = fmaf(s[tq][tt], bflo(kvp[tt][j]), o0);
                        o1 = fmaf(s[tq][tt], bfhi(kvp[tt][j]), o1);
                    }
                    Ot[(tq * 64 + cb + 2 * j) * OTP2 + nl] = __float2bfloat16(o0);
                    Ot[(tq * 64 + cb + 2 * j + 1) * OTP2 + nl] = __float2bfloat16(o1);
                }
            }
        }
    }
    __syncthreads();

    const int mg = wid >> 1, nh = wid & 1;
    const int g = lane >> 2, tg = lane & 3;
    const uint32_t ws_b = smem_u32(Ws);
    const uint32_t ot_b = smem_u32(Ot);
    const uint32_t aAddr0 = ws_b + (uint32_t)((mg * 16 + (lane & 15)) * 72 + (lane >> 4) * 8) * 2;
    const int krow_l = (lane & 7) + ((lane >> 3) & 1) * 8;
    const int np_l = nh * 32 + ((lane >> 4) & 1) * 8;

    uint32_t Af[4][4];
#pragma unroll
    for (int kk = 0; kk < 4; kk++)
        ldsm_x4(Af[kk], aAddr0 + (uint32_t)kk * 32);

    float ps[2], pq[2];
    ps[0] = ps[1] = pq[0] = pq[1] = 0.f;

    for (int t = 0; t < 8; t++) {
        float acc[4][4];
#pragma unroll
        for (int nt = 0; nt < 4; nt++)
#pragma unroll
            for (int i = 0; i < 4; i++) acc[nt][i] = 0.f;

#pragma unroll
        for (int kk = 0; kk < 4; kk++) {
            uint32_t Bf0[4], Bf1[4];
            const uint32_t base =
                ot_b + (uint32_t)((t * 64 + kk * 16 + krow_l) * OTP2 + np_l) * 2;
            ldsm_x4_t(Bf0, base);
            ldsm_x4_t(Bf1, base + 32);
            mma_bf16(acc[0], Af[kk][0], Af[kk][1], Af[kk][2], Af[kk][3], Bf0[0], Bf0[1]);
            mma_bf16(acc[1], Af[kk][0], Af[kk][1], Af[kk][2], Af[kk][3], Bf0[2], Bf0[3]);
            mma_bf16(acc[2], Af[kk][0], Af[kk][1], Af[kk][2], Af[kk][3], Bf1[0], Bf1[1]);
            mma_bf16(acc[3], Af[kk][0], Af[kk][1], Af[kk][2], Af[kk][3], Bf1[2], Bf1[3]);
        }

#pragma unroll
        for (int r = 0; r < 2; r++) {
            const int co = mg * 16 + r * 8 + g;
            const float bb = __ldg(&bias[co]);
            const float A0 = s_c0[co], B0 = s_c0[64 + co];
            const size_t rowb = ((size_t)(b * C_ + co) * T_ + t) * S_ + jb;
#pragma unroll
            for (int nt = 0; nt < 4; nt++) {
                const int px = nh * 32 + nt * 8 + tg * 2;
                uint32_t u = *(const uint32_t*)&g_xh[rowb + px];
                __nv_bfloat162 bp = *(__nv_bfloat162*)&u;
                float zx = lk(fmaf(__bfloat162float(bp.x), A0, B0)) + acc[nt][r * 2] + bb;
                float zy = lk(fmaf(__bfloat162float(bp.y), A0, B0)) + acc[nt][r * 2 + 1] + bb;
                *(uint32_t*)&g_zh[rowb + px] = packbf(zx, zy);
                ps[r] += zx + zy;
                pq[r] += zx * zx + zy * zy;
            }
        }
    }

#pragma unroll
    for (int r = 0; r < 2; r++) {
        ps[r] += __shfl_xor_sync(0xffffffffu, ps[r], 1);
        ps[r] += __shfl_xor_sync(0xffffffffu, ps[r], 2);
        pq[r] += __shfl_xor_sync(0xffffffffu, pq[r], 1);
        pq[r] += __shfl_xor_sync(0xffffffffu, pq[r], 2);
    }
    if ((lane & 3) == 0) {
#pragma unroll
        for (int r = 0; r < 2; r++) {
            const int co = mg * 16 + r * 8 + g;
            atomicAdd(&s_st[co], ps[r]);
            atomicAdd(&s_st[64 + co], pq[r]);
        }
    }
    __syncthreads();
    if (tid < 128) atomicAdd(&g_sum1[tid], s_st[tid]);
}

// ---------------- spatial mean of leaky(bn1(z)), coef1 inline ----------------
__global__ void __launch_bounds__(256) k_mean(const float* __restrict__ bn1g,
                                              const float* __restrict__ bn1b) {
    const int bid = blockIdx.x;
    const int c = (bid >> 3) & 63;
    const float inv = 1.0f / CNT_;
    const float mu = g_sum1[c] * inv;
    const float var = g_sum1[64 + c] * inv - mu * mu;
    const float A = bn1g[c] * rsqrtf(var + 1e-5f);
    const float Bv = bn1b[c] - mu * A;
    const uint32_t* p = (const uint32_t*)(g_zh + (size_t)bid * S_);
    float s = 0.f;
    for (int i = threadIdx.x; i < S_ / 2; i += 256) {
        uint32_t u = p[i];
        __nv_bfloat162 bp = *(__nv_bfloat162*)&u;
        s += lk(fmaf(__bfloat162float(bp.x), A, Bv));
        s += lk(fmaf(__bfloat162float(bp.y), A, Bv));
    }
#pragma unroll
    for (int off = 16; off; off >>= 1) s += __shfl_down_sync(0xffffffffu, s, off);
    __shared__ float wa[8];
    const int lane = threadIdx.x & 31, wid = threadIdx.x >> 5;
    if (lane == 0) wa[wid] = s;
    __syncthreads();
    if (threadIdx.x == 0) {
        float ts = 0.f;
#pragma unroll
        for (int i = 0; i < 8; i++) ts += wa[i];
        g_m[bid] = ts * (1.0f / (float)S_);
    }
}

// ---------------- dynamic depthwise 5x5 conv (kernel-gen fused) ----------------
__global__ void __launch_bounds__(256) k_dynconv(const float* __restrict__ h,
                                                 const float* __restrict__ w1,
                                                 const float* __restrict__ b1,
                                                 float* __restrict__ out) {
    __shared__ float sp[100 * 100];
    __shared__ float sk[25];
    const int bid = blockIdx.x;
    const int b = bid >> 9;
    const int t = bid & 7;
    const int tid = threadIdx.x;
    const float* base = h + (size_t)bid * S_;

    for (int i = tid; i < 10000; i += 256) sp[i] = 0.f;
    if (tid < 25) {
        float a = __ldg(&b1[tid]);
#pragma unroll 8
        for (int c = 0; c < 64; c++)
            a = fmaf(g_m[(b * C_ + c) * T_ + t], __ldg(&w1[tid * 64 + c]), a);
        sk[tid] = a;
    }
    __syncthreads();
    for (int i = tid; i < S_; i += 256) {
        const int r = i / 96, col = i - r * 96;
        sp[(r + 2) * 100 + col + 2] = base[i];
    }
    __syncthreads();

    float kr[25];
#pragma unroll
    for (int q = 0; q < 25; q++) kr[q] = sk[q];

    float* ob = out + (size_t)bid * S_;
    for (int i = tid; i < S_; i += 256) {
        const int r = i / 96, col = i - r * 96;
        const float* pp = &sp[r * 100 + col];
        float a = 0.f;
#pragma unroll
        for (int ii = 0; ii < 5; ii++)
#pragma unroll
            for (int jj = 0; jj < 5; jj++)
                a = fmaf(pp[ii * 100 + jj], kr[ii * 5 + jj], a);
        ob[i] = a;
    }
}

// ---------------- launch ----------------
extern "C" void kernel_launch(void* const* d_in, const int* in_sizes, int n_in,
                              void* d_out, int out_size) {
    const float* h       = (const float*)d_in[0];
    const float* conv0_w = (const float*)d_in[1];
    const float* conv0_b = (const float*)d_in[2];
    const float* bn0_g   = (const float*)d_in[3];
    const float* bn0_b   = (const float*)d_in[4];
    const float* bn1_g   = (const float*)d_in[5];
    const float* bn1_b   = (const float*)d_in[6];
    const float* inW     = (const float*)d_in[7];
    const float* inB     = (const float*)d_in[8];
    const float* outW    = (const float*)d_in[9];
    const float* outB    = (const float*)d_in[10];
    const float* c1w     = (const float*)d_in[11];
    const float* c1b     = (const float*)d_in[12];
    float* out = (float*)d_out;

    cudaFuncSetAttribute(k_conv0_mma, cudaFuncAttributeMaxDynamicSharedMemorySize,
                         SM_CONV_TOT);
    cudaFuncSetAttribute(k_qkv_mma, cudaFuncAttributeMaxDynamicSharedMemorySize,
                         QSM_TOT);
    cudaFuncSetAttribute(k_attn_fused, cudaFuncAttributeMaxDynamicSharedMemorySize,
                         SM_ATTN_TOT);

    k_prep<<<144, 256>>>(conv0_w, inW, outW);
    k_conv0_mma<<<dim3(4, B_ * T_), 512, SM_CONV_TOT>>>(h, conv0_b);
    k_qkv_mma<<<dim3(4, B_ * T_), 512, QSM_TOT>>>(inB, bn0_g, bn0_b);
    k_attn_fused<<<N_ / 64, 256, SM_ATTN_TOT>>>(outB, bn0_g, bn0_b);
    k_mean<<<B_ * C_ * T_, 256>>>(bn1_g, bn1_b);
    k_dynconv<<<B_ * C_ * T_, 256>>>(h, c1w, c1b, out);
}

// round 17
// speedup vs baseline: 1.0971x; 1.0766x over previous
#include <cuda_runtime.h>
#include <cuda_bf16.h>
#include <cstdint>

// Problem constants
#define B_ 4
#define C_ 64
#define T_ 8
#define X_ 96
#define Y_ 96
#define S_ 9216            // X_*Y_
#define N_ 36864           // B_*S_
#define TS_ 73728          // T_*S_
#define TOTAL_ 18874368    // B_*C_*T_*S_
#define QSZ_ 18874368      // T_*C_*N_
#define CNT_ 294912.0f     // B_*T_*S_

// -------- scratch (device globals; no runtime allocation) --------
__device__ __nv_bfloat16 g_xh[TOTAL_];            // conv0 raw output (pre-BN0), bf16
__device__ uint32_t g_qkvp[768 * N_];             // qkv packed d-pairs: row=((z*8+h)*8+t)*4+jp
__device__ __nv_bfloat16 g_zh[TOTAL_];            // residual + out_proj (pre-BN1), bf16
__device__ float g_sum0[128];
__device__ float g_sum1[128];
__device__ float g_m[B_ * C_ * T_];
__device__ __align__(16) __nv_bfloat16 g_wk[64 * 576];   // conv0 [co][k], k=tap*64+ci
__device__ __align__(16) __nv_bfloat16 g_wqkv[192 * 64]; // in_proj bf16
__device__ __align__(16) __nv_bfloat16 g_wout[64 * 64];  // out_proj bf16

__device__ __forceinline__ float lk(float v) { return v >= 0.f ? v : 0.01f * v; }

// FFMA-only exp
__device__ __forceinline__ float fexp(float x) {
    const float L2E = 1.4426950408889634f;
    float t = fmaf(x, L2E, 12582912.0f);
    int ii = __float_as_int(t) - 0x4B400000;
    float i = t - 12582912.0f;
    float f = fmaf(x, L2E, -i);
    float p = 1.3333558146e-3f;
    p = fmaf(p, f, 9.6181291918e-3f);
    p = fmaf(p, f, 5.5504108664e-2f);
    p = fmaf(p, f, 2.4022650695e-1f);
    p = fmaf(p, f, 6.9314718056e-1f);
    p = fmaf(p, f, 1.0f);
    return __int_as_float(__float_as_int(p) + (ii << 23));
}

__device__ __forceinline__ float bflo(uint32_t u) { return __int_as_float(u << 16); }
__device__ __forceinline__ float bfhi(uint32_t u) { return __int_as_float(u & 0xFFFF0000u); }

__device__ __forceinline__ void mma_bf16(float* c, uint32_t a0, uint32_t a1,
                                         uint32_t a2, uint32_t a3,
                                         uint32_t b0, uint32_t b1) {
    asm volatile(
        "mma.sync.aligned.m16n8k16.row.col.f32.bf16.bf16.f32 "
        "{%0,%1,%2,%3}, {%4,%5,%6,%7}, {%8,%9}, {%0,%1,%2,%3};"
        : "+f"(c[0]), "+f"(c[1]), "+f"(c[2]), "+f"(c[3])
        : "r"(a0), "r"(a1), "r"(a2), "r"(a3), "r"(b0), "r"(b1));
}

__device__ __forceinline__ uint32_t packbf(float a, float b) {
    __nv_bfloat162 p = __floats2bfloat162_rn(a, b);
    return *(uint32_t*)&p;
}

__device__ __forceinline__ uint32_t smem_u32(const void* p) {
    uint32_t a;
    asm("{ .reg .u64 t; cvta.to.shared.u64 t, %1; cvt.u32.u64 %0, t; }" : "=r"(a) : "l"(p));
    return a;
}

__device__ __forceinline__ void ldsm_x4(uint32_t* r, uint32_t addr) {
    asm volatile("ldmatrix.sync.aligned.m8n8.x4.shared.b16 {%0,%1,%2,%3}, [%4];"
        : "=r"(r[0]), "=r"(r[1]), "=r"(r[2]), "=r"(r[3]) : "r"(addr));
}
__device__ __forceinline__ void ldsm_x4_t(uint32_t* r, uint32_t addr) {
    asm volatile("ldmatrix.sync.aligned.m8n8.x4.trans.shared.b16 {%0,%1,%2,%3}, [%4];"
        : "=r"(r[0]), "=r"(r[1]), "=r"(r[2]), "=r"(r[3]) : "r"(addr));
}

// ===================== combined prep =====================
__global__ void k_prep(const float* __restrict__ w, const float* __restrict__ inW,
                       const float* __restrict__ outW) {
    int i = blockIdx.x * 256 + threadIdx.x;
    if (i < 128) { g_sum0[i] = 0.f; g_sum1[i] = 0.f; }
    if (i < 64 * 576) {
        int co = i / 576, k = i - co * 576;
        g_wk[i] = __float2bfloat16(w[(co * 64 + (k & 63)) * 9 + (k >> 6)]);
    }
    if (i < 192 * 64) g_wqkv[i] = __float2bfloat16(inW[i]);
    if (i < 64 * 64) g_wout[i] = __float2bfloat16(outW[i]);
}

// ===================== conv0: persistent bf16 mma + ldmatrix (R14 form) ==========
#define SINW 72
#define ROWE (98 * SINW)
#define RING 8
#define WKS 584
#define SM_WK_OFF (RING * ROWE * 2)
#define SM_CONV_TOT (SM_WK_OFF + 64 * WKS * 2)

__device__ __forceinline__ void stage_row(__nv_bfloat16* sin_s, const float* hb,
                                          int gx, int tid) {
    const int slot = (gx + 8) & 7;
    __nv_bfloat16* dst = sin_s + slot * ROWE;
    if ((unsigned)gx >= 96u) {
        for (int e = tid; e < 6144; e += 512) {
            int ci = e / 96, y = e - ci * 96;
            dst[(y + 1) * SINW + ci] = __float2bfloat16(0.f);
        }
    } else {
        const float* hp = hb + (size_t)gx * 96;
        for (int e = tid; e < 6144; e += 512) {
            int ci = e / 96, y = e - ci * 96;
            dst[(y + 1) * SINW + ci] = __float2bfloat16(hp[(size_t)ci * TS_ + y]);
        }
    }
    if (tid < 64) dst[tid] = __float2bfloat16(0.f);
    else if (tid < 128) dst[97 * SINW + (tid - 64)] = __float2bfloat16(0.f);
}

__global__ void __launch_bounds__(512)
k_conv0_mma(const float* __restrict__ h, const float* __restrict__ bias) {
    extern __shared__ char smem[];
    __nv_bfloat16* sin_s = (__nv_bfloat16*)smem;
    __nv_bfloat16* wk_s = (__nv_bfloat16*)(smem + SM_WK_OFF);
    __shared__ float s_st[128];

    const int tid = threadIdx.x, lane = tid & 31, wid = tid >> 5;
    const int group = blockIdx.x, bt = blockIdx.y, b = bt >> 3, t = bt & 7;
    const float* hb = h + (size_t)b * (64 * TS_) + (size_t)t * S_;

    if (tid < 128) s_st[tid] = 0.f;
    {
        const uint4* src = (const uint4*)g_wk;
        for (int e = tid; e < 4608; e += 512) {
            int co = e / 72, q = e - co * 72;
            *(uint4*)&wk_s[co * WKS + q * 8] = src[e];
        }
    }
    {
        const int p0 = group * 2304;
        const int xlo = p0 / 96, xhi = (p0 + 255) / 96;
        for (int gx = xlo - 1; gx <= xhi + 1; gx++) stage_row(sin_s, hb, gx, tid);
    }
    __syncthreads();

    const int mg = wid >> 1, nh = wid & 1;
    const int g = lane >> 2, tg = lane & 3;

    const uint32_t sin_b = smem_u32(sin_s);
    const uint32_t wk_b = smem_u32(wk_s);

    uint32_t wkaddr[2];
    {
        const int koff = ((lane >> 3) & 1) * 8;
        const int cosub = (lane & 7) + ((lane >> 4) & 1) * 8;
#pragma unroll
        for (int ntp = 0; ntp < 2; ntp++) {
            const int co = nh * 32 + ntp * 16 + cosub;
            wkaddr[ntp] = wk_b + (uint32_t)(co * WKS + koff) * 2;
        }
    }
    const uint32_t khiA = (uint32_t)((lane >> 4) * 16);

    float bv[4][2];
#pragma unroll
    for (int nt = 0; nt < 4; nt++) {
        const int co0 = nh * 32 + nt * 8 + tg * 2;
        bv[nt][0] = __ldg(&bias[co0]);
        bv[nt][1] = __ldg(&bias[co0 + 1]);
    }

    float st_s[8], st_q[8];
#pragma unroll
    for (int i = 0; i < 8; i++) { st_s[i] = 0.f; st_q[i] = 0.f; }

    __nv_bfloat16* obB = g_xh + (size_t)b * (64 * TS_) + (size_t)t * S_;

    for (int ti = 0; ti < 9; ti++) {
        const int p0 = group * 2304 + ti * 256;
        const int xhi = (p0 + 255) / 96;
        if (ti < 8) {
            const int xhin = (p0 + 511) / 96;
            for (int gx = xhi + 2; gx <= xhin + 1; gx++) stage_row(sin_s, hb, gx, tid);
        }

        uint32_t aRB[2][3];
        {
            const int plbase = p0 + mg * 32 + (lane & 15);
#pragma unroll
            for (int mt = 0; mt < 2; mt++) {
                const int pl = plbase + mt * 16;
                const int px = pl / 96, py = pl - px * 96;
#pragma unroll
                for (int dx = 0; dx < 3; dx++)
                    aRB[mt][dx] = sin_b +
                        (uint32_t)(((px + dx + 7) & 7) * ROWE + py * SINW) * 2 + khiA;
            }
        }

        float acc[2][4][4];
#pragma unroll
        for (int mt = 0; mt < 2; mt++)
#pragma unroll
            for (int nt = 0; nt < 4; nt++)
#pragma unroll
                for (int i = 0; i < 4; i++) acc[mt][nt][i] = 0.f;

#pragma unroll
        for (int tap = 0; tap < 9; tap++) {
            const int dx = tap / 3, dy = tap - dx * 3;
            const uint32_t dyoff = (uint32_t)(dy * SINW) * 2;
#pragma unroll
            for (int kk = 0; kk < 4; kk++) {
                const uint32_t ko2 = (uint32_t)kk * 32;
                uint32_t A0[4], A1[4], Bf0[4], Bf1[4];
                ldsm_x4(A0, aRB[0][dx] + dyoff + ko2);
                ldsm_x4(A1, aRB[1][dx] + dyoff + ko2);
                const uint32_t bk = (uint32_t)(tap * 64 + kk * 16) * 2;
                ldsm_x4(Bf0, wkaddr[0] + bk);
                ldsm_x4(Bf1, wkaddr[1] + bk);
                mma_bf16(acc[0][0], A0[0], A0[1], A0[2], A0[3], Bf0[0], Bf0[1]);
                mma_bf16(acc[1][0], A1[0], A1[1], A1[2], A1[3], Bf0[0], Bf0[1]);
                mma_bf16(acc[0][1], A0[0], A0[1], A0[2], A0[3], Bf0[2], Bf0[3]);
                mma_bf16(acc[1][1], A1[0], A1[1], A1[2], A1[3], Bf0[2], Bf0[3]);
                mma_bf16(acc[0][2], A0[0], A0[1], A0[2], A0[3], Bf1[0], Bf1[1]);
                mma_bf16(acc[1][2], A1[0], A1[1], A1[2], A1[3], Bf1[0], Bf1[1]);
                mma_bf16(acc[0][3], A0[0], A0[1], A0[2], A0[3], Bf1[2], Bf1[3]);
                mma_bf16(acc[1][3], A1[0], A1[1], A1[2], A1[3], Bf1[2], Bf1[3]);
            }
        }

        __nv_bfloat16* ob = obB + p0;
#pragma unroll
        for (int nt = 0; nt < 4; nt++) {
            const int co0 = nh * 32 + nt * 8 + tg * 2;
#pragma unroll
            for (int mt = 0; mt < 2; mt++) {
                const int pr = mg * 32 + mt * 16 + g;
                float v0 = acc[mt][nt][0] + bv[nt][0];
                float v1 = acc[mt][nt][1] + bv[nt][1];
                float v2 = acc[mt][nt][2] + bv[nt][0];
                float v3 = acc[mt][nt][3] + bv[nt][1];
                ob[(size_t)co0 * TS_ + pr]           = __float2bfloat16(v0);
                ob[(size_t)(co0 + 1) * TS_ + pr]     = __float2bfloat16(v1);
                ob[(size_t)co0 * TS_ + pr + 8]       = __float2bfloat16(v2);
                ob[(size_t)(co0 + 1) * TS_ + pr + 8] = __float2bfloat16(v3);
                st_s[nt * 2]     += v0 + v2;
                st_q[nt * 2]     += v0 * v0 + v2 * v2;
                st_s[nt * 2 + 1] += v1 + v3;
                st_q[nt * 2 + 1] += v1 * v1 + v3 * v3;
            }
        }
        __syncthreads();
    }

#pragma unroll
    for (int i = 0; i < 8; i++) {
        st_s[i] += __shfl_xor_sync(0xffffffffu, st_s[i], 4);
        st_s[i] += __shfl_xor_sync(0xffffffffu, st_s[i], 8);
        st_s[i] += __shfl_xor_sync(0xffffffffu, st_s[i], 16);
        st_q[i] += __shfl_xor_sync(0xffffffffu, st_q[i], 4);
        st_q[i] += __shfl_xor_sync(0xffffffffu, st_q[i], 8);
        st_q[i] += __shfl_xor_sync(0xffffffffu, st_q[i], 16);
    }
    if (lane < 4) {
#pragma unroll
        for (int nt = 0; nt < 4; nt++)
#pragma unroll
            for (int r = 0; r < 2; r++) {
                const int co = nh * 32 + nt * 8 + lane * 2 + r;
                atomicAdd(&s_st[co], st_s[nt * 2 + r]);
                atomicAdd(&s_st[64 + co], st_q[nt * 2 + r]);
            }
    }
    __syncthreads();
    if (tid < 128) atomicAdd(&g_sum0[tid], s_st[tid]);
}

// ---------------- qkv: persistent bf16 mma, writes packed d-pair layout ----------------
#define QSM_WS (2 * 128 * 72 * 2)
#define QSM_TOT (QSM_WS + 192 * 72 * 2)

__global__ void __launch_bounds__(512) k_qkv_mma(const float* __restrict__ bias,
                                                 const float* __restrict__ bn0g,
                                                 const float* __restrict__ bn0b) {
    extern __shared__ char smem[];
    __nv_bfloat16* Xt = (__nv_bfloat16*)smem;
    __nv_bfloat16* Ws = (__nv_bfloat16*)(smem + QSM_WS);
    __shared__ float s_c[128];
    const int tid = threadIdx.x, lane = tid & 31, wid = tid >> 5;
    const int group = blockIdx.x;
    const int bt = blockIdx.y, b = bt >> 3, t = bt & 7;

    if (tid < 64) {
        const float inv = 1.0f / CNT_;
        float mu = g_sum0[tid] * inv;
        float var = g_sum0[64 + tid] * inv - mu * mu;
        float A = bn0g[tid] * rsqrtf(var + 1e-5f);
        s_c[tid] = A;
        s_c[64 + tid] = bn0b[tid] - mu * A;
    }
    {
        const uint4* src = (const uint4*)g_wqkv;
        for (int e = tid; e < 1536; e += 512) {
            int co = e >> 3, q = e & 7;
            *(uint4*)&Ws[co * 72 + q * 8] = src[e];
        }
    }
    __syncthreads();

    const __nv_bfloat16* xbase = g_xh + ((size_t)(b * C_) * T_ + t) * S_;
    {
        const __nv_bfloat16* xb = xbase + group * 18 * 128;
        for (int e = tid; e < 4096; e += 512) {
            int kp = e >> 7, n = e & 127;
            int k0 = kp * 2;
            float x0 = __bfloat162float(xb[(size_t)k0 * TS_ + n]);
            float x1 = __bfloat162float(xb[(size_t)(k0 + 1) * TS_ + n]);
            *(uint32_t*)&Xt[n * 72 + k0] =
                packbf(lk(fmaf(x0, s_c[k0], s_c[64 + k0])),
                       lk(fmaf(x1, s_c[k0 + 1], s_c[64 + k0 + 1])));
        }
    }
    __syncthreads();

    const int mg = wid >> 2, ng = wid & 3;
    const int g = lane >> 2, tg = lane & 3;
    const uint32_t ws_b = smem_u32(Ws), xt_b = smem_u32(Xt);
    const uint32_t aAddr = ws_b +
        (uint32_t)((mg * 48 + (lane & 15)) * 72 + (lane >> 4) * 8) * 2;
    const int nsub = (lane & 7) + ((lane >> 4) & 1) * 8;
    const int koff = ((lane >> 3) & 1) * 8;
    const uint32_t bAddrBase = (uint32_t)((ng * 32 + nsub) * 72 + koff) * 2;

    uint32_t Af[3][4][4];
#pragma unroll
    for (int kk = 0; kk < 4; kk++) {
        ldsm_x4(Af[0][kk], aAddr + (uint32_t)kk * 32);
        ldsm_x4(Af[1][kk], aAddr + 16 * 72 * 2 + (uint32_t)kk * 32);
        ldsm_x4(Af[2][kk], aAddr + 32 * 72 * 2 + (uint32_t)kk * 32);
    }

    float bb[3][2];
#pragma unroll
    for (int mt = 0; mt < 3; mt++) {
        const int co = mg * 48 + mt * 16 + g;
        bb[mt][0] = __ldg(&bias[co]);
        bb[mt][1] = __ldg(&bias[co + 8]);
    }

    const int par = g & 1;

    for (int ti = 0; ti < 18; ti++) {
        const int j0 = (group * 18 + ti) * 128;
        const uint32_t xtb = xt_b + (uint32_t)(ti & 1) * (128 * 72 * 2);
        if (ti < 17) {
            __nv_bfloat16* XtN = Xt + ((ti + 1) & 1) * (128 * 72);
            const __nv_bfloat16* xb = xbase + j0 + 128;
            for (int e = tid; e < 4096; e += 512) {
                int kp = e >> 7, n = e & 127;
                int k0 = kp * 2;
                float x0 = __bfloat162float(xb[(size_t)k0 * TS_ + n]);
                float x1 = __bfloat162float(xb[(size_t)(k0 + 1) * TS_ + n]);
                *(uint32_t*)&XtN[n * 72 + k0] =
                    packbf(lk(fmaf(x0, s_c[k0], s_c[64 + k0])),
                           lk(fmaf(x1, s_c[k0 + 1], s_c[64 + k0 + 1])));
            }
        }

        float acc[3][4][4];
#pragma unroll
        for (int mt = 0; mt < 3; mt++)
#pragma unroll
            for (int nt = 0; nt < 4; nt++)
#pragma unroll
                for (int i = 0; i < 4; i++) acc[mt][nt][i] = 0.f;

#pragma unroll
        for (int kk = 0; kk < 4; kk++) {
            const uint32_t ko2 = (uint32_t)kk * 32;
            uint32_t Bf0[4], Bf1[4];
            ldsm_x4(Bf0, xtb + bAddrBase + ko2);
            ldsm_x4(Bf1, xtb + bAddrBase + 16 * 72 * 2 + ko2);
            mma_bf16(acc[0][0], Af[0][kk][0], Af[0][kk][1], Af[0][kk][2], Af[0][kk][3], Bf0[0], Bf0[1]);
            mma_bf16(acc[1][0], Af[1][kk][0], Af[1][kk][1], Af[1][kk][2], Af[1][kk][3], Bf0[0], Bf0[1]);
            mma_bf16(acc[2][0], Af[2][kk][0], Af[2][kk][1], Af[2][kk][2], Af[2][kk][3], Bf0[0], Bf0[1]);
            mma_bf16(acc[0][1], Af[0][kk][0], Af[0][kk][1], Af[0][kk][2], Af[0][kk][3], Bf0[2], Bf0[3]);
            mma_bf16(acc[1][1], Af[1][kk][0], Af[1][kk][1], Af[1][kk][2], Af[1][kk][3], Bf0[2], Bf0[3]);
            mma_bf16(acc[2][1], Af[2][kk][0], Af[2][kk][1], Af[2][kk][2], Af[2][kk][3], Bf0[2], Bf0[3]);
            mma_bf16(acc[0][2], Af[0][kk][0], Af[0][kk][1], Af[0][kk][2], Af[0][kk][3], Bf1[0], Bf1[1]);
            mma_bf16(acc[1][2], Af[1][kk][0], Af[1][kk][1], Af[1][kk][2], Af[1][kk][3], Bf1[0], Bf1[1]);
            mma_bf16(acc[2][2], Af[2][kk][0], Af[2][kk][1], Af[2][kk][2], Af[2][kk][3], Bf1[0], Bf1[1]);
            mma_bf16(acc[0][3], Af[0][kk][0], Af[0][kk][1], Af[0][kk][2], Af[0][kk][3], Bf1[2], Bf1[3]);
            mma_bf16(acc[1][3], Af[1][kk][0], Af[1][kk][1], Af[1][kk][2], Af[1][kk][3], Bf1[2], Bf1[3]);
            mma_bf16(acc[2][3], Af[2][kk][0], Af[2][kk][1], Af[2][kk][2], Af[2][kk][3], Bf1[2], Bf1[3]);
        }

        // writeout: packed d-pair layout. co and co^1 (d even/odd) are in lanes g, g^1
        // (lane^4). Even lane packs column n; odd lane packs column n+1.
        const int ncolbase = b * S_ + j0 + ng * 32 + tg * 2;
#pragma unroll
        for (int mt = 0; mt < 3; mt++) {
#pragma unroll
            for (int r = 0; r < 2; r++) {
                const int co = mg * 48 + mt * 16 + r * 8 + g;
                const int z = co >> 6, hh = (co >> 3) & 7, jp = (co & 7) >> 1;
                const uint32_t row = (uint32_t)(((z * 8 + hh) * 8 + t) * 4 + jp);
                const float bvv = bb[mt][r];
#pragma unroll
                for (int nt = 0; nt < 4; nt++) {
                    float v0 = acc[mt][nt][r * 2] + bvv;
                    float v1 = acc[mt][nt][r * 2 + 1] + bvv;
                    float ex0 = __shfl_xor_sync(0xffffffffu, v0, 4);
                    float ex1 = __shfl_xor_sync(0xffffffffu, v1, 4);
                    uint32_t pk = par ? packbf(ex1, v1) : packbf(v0, ex0);
                    g_qkvp[(size_t)row * N_ + (ncolbase + nt * 8 + par)] = pk;
                }
            }
        }
        __syncthreads();
    }
}

// ---------------- fused attention + out_proj (packed u32 qkv loads) ----------
#define OTP2 72
#define SM_WS_OFF (8 * 64 * OTP2 * 2)
#define SM_ATTN_TOT (SM_WS_OFF + 64 * 72 * 2)

__global__ void __launch_bounds__(256, 2)
k_attn_fused(const float* __restrict__ bias, const float* __restrict__ bn0g,
             const float* __restrict__ bn0b) {
    extern __shared__ char smem[];
    __nv_bfloat16* Ot = (__nv_bfloat16*)smem;
    __nv_bfloat16* Ws = (__nv_bfloat16*)(smem + SM_WS_OFF);
    __shared__ float s_st[128];
    __shared__ float s_c0[128];
    const int tid = threadIdx.x, lane = tid & 31, wid = tid >> 5;
    const int j0 = blockIdx.x * 64;
    const int b = j0 / S_;
    const int jb = j0 - b * S_;

    if (tid < 128) s_st[tid] = 0.f;
    if (tid >= 128 && tid < 192) {
        const int c = tid - 128;
        const float inv = 1.0f / CNT_;
        float mu = g_sum0[c] * inv;
        float var = g_sum0[64 + c] * inv - mu * mu;
        float A = bn0g[c] * rsqrtf(var + 1e-5f);
        s_c0[c] = A;
        s_c0[64 + c] = bn0b[c] - mu * A;
    }
    {
        const uint4* src = (const uint4*)g_wout;
        for (int e = tid; e < 512; e += 256) {
            int co = e >> 3, q = e & 7;
            *(uint4*)&Ws[co * 72 + q * 8] = src[e];
        }
    }

    // ---- phase 1: attention, 64 n x 8 heads; thread = (n, 2 heads) ----
    {
        const int nl = tid & 63;
        const int hp = tid >> 6;
        const int n = j0 + nl;
        const float scale = 0.3535533905932738f;
        for (int i = 0; i < 2; i++) {
            const int hh = hp * 2 + i;
            const int cb = hh * 8;
            const size_t rq = (size_t)(hh * 32) * N_ + n;          // z=0
            const size_t rk = (size_t)(256 + hh * 32) * N_ + n;    // z=1
            const size_t rv = (size_t)(512 + hh * 32) * N_ + n;    // z=2
            uint32_t kvp[8][4];
#pragma unroll
            for (int tt = 0; tt < 8; tt++)
#pragma unroll
                for (int j = 0; j < 4; j++)
                    kvp[tt][j] = g_qkvp[rk + (size_t)(tt * 4 + j) * N_];
            // --- dot products (k dies after) ---
            float s[8][8], mx[8];
#pragma unroll
            for (int tq = 0; tq < 8; tq++) {
                float q[8];
#pragma unroll
                for (int j = 0; j < 4; j++) {
                    uint32_t qu = g_qkvp[rq + (size_t)(tq * 4 + j) * N_];
                    q[2 * j] = bflo(qu) * scale;
                    q[2 * j + 1] = bfhi(qu) * scale;
                }
                float m = -1e30f;
#pragma unroll
                for (int tt = 0; tt < 8; tt++) {
                    float a = 0.f;
#pragma unroll
                    for (int j = 0; j < 4; j++) {
                        a = fmaf(q[2 * j], bflo(kvp[tt][j]), a);
                        a = fmaf(q[2 * j + 1], bfhi(kvp[tt][j]), a);
                    }
                    s[tq][tt] = a;
                    m = fmaxf(m, a);
                }
                mx[tq] = m;
            }
            // --- issue v loads (independent); softmax hides their latency ---
#pragma unroll
            for (int tt = 0; tt < 8; tt++)
#pragma unroll
                for (int j = 0; j < 4; j++)
                    kvp[tt][j] = g_qkvp[rv + (size_t)(tt * 4 + j) * N_];
            // --- softmax ---
#pragma unroll
            for (int tq = 0; tq < 8; tq++) {
                float sum = 0.f;
#pragma unroll
                for (int tt = 0; tt < 8; tt++) { s[tq][tt] = fexp(s[tq][tt] - mx[tq]); sum += s[tq][tt]; }
                const float inv = 1.0f / sum;
#pragma unroll
                for (int tt = 0; tt < 8; tt++) s[tq][tt] *= inv;
            }
            // --- o = s @ v ---
#pragma unroll
            for (int tq = 0; tq < 8; tq++) {
#pragma unroll
                for (int j = 0; j < 4; j++) {
                    float o0 = 0.f, o1 = 0.f;
#pragma unroll
                    for (int tt = 0; tt < 8; tt++) {
                        o0 = fmaf(s[tq][tt], bflo(kvp[tt][j]), o0);
                        o1 = fmaf(s[tq][tt], bfhi(kvp[tt][j]), o1);
                    }
                    Ot[(tq * 64 + cb + 2 * j) * OTP2 + nl] = __float2bfloat16(o0);
                    Ot[(tq * 64 + cb + 2 * j + 1) * OTP2 + nl] = __float2bfloat16(o1);
                }
            }
        }
    }
    __syncthreads();

    const int mg = wid >> 1, nh = wid & 1;
    const int g = lane >> 2, tg = lane & 3;
    const uint32_t ws_b = smem_u32(Ws);
    const uint32_t ot_b = smem_u32(Ot);
    const uint32_t aAddr0 = ws_b + (uint32_t)((mg * 16 + (lane & 15)) * 72 + (lane >> 4) * 8) * 2;
    const int krow_l = (lane & 7) + ((lane >> 3) & 1) * 8;
    const int np_l = nh * 32 + ((lane >> 4) & 1) * 8;

    uint32_t Af[4][4];
#pragma unroll
    for (int kk = 0; kk < 4; kk++)
        ldsm_x4(Af[kk], aAddr0 + (uint32_t)kk * 32);

    float ps[2], pq[2];
    ps[0] = ps[1] = pq[0] = pq[1] = 0.f;

    for (int t = 0; t < 8; t++) {
        float acc[4][4];
#pragma unroll
        for (int nt = 0; nt < 4; nt++)
#pragma unroll
            for (int i = 0; i < 4; i++) acc[nt][i] = 0.f;

#pragma unroll
        for (int kk = 0; kk < 4; kk++) {
            uint32_t Bf0[4], Bf1[4];
            const uint32_t base =
                ot_b + (uint32_t)((t * 64 + kk * 16 + krow_l) * OTP2 + np_l) * 2;
            ldsm_x4_t(Bf0, base);
            ldsm_x4_t(Bf1, base + 32);
            mma_bf16(acc[0], Af[kk][0], Af[kk][1], Af[kk][2], Af[kk][3], Bf0[0], Bf0[1]);
            mma_bf16(acc[1], Af[kk][0], Af[kk][1], Af[kk][2], Af[kk][3], Bf0[2], Bf0[3]);
            mma_bf16(acc[2], Af[kk][0], Af[kk][1], Af[kk][2], Af[kk][3], Bf1[0], Bf1[1]);
            mma_bf16(acc[3], Af[kk][0], Af[kk][1], Af[kk][2], Af[kk][3], Bf1[2], Bf1[3]);
        }

#pragma unroll
        for (int r = 0; r < 2; r++) {
            const int co = mg * 16 + r * 8 + g;
            const float bb = __ldg(&bias[co]);
            const float A0 = s_c0[co], B0 = s_c0[64 + co];
            const size_t rowb = ((size_t)(b * C_ + co) * T_ + t) * S_ + jb;
#pragma unroll
            for (int nt = 0; nt < 4; nt++) {
                const int px = nh * 32 + nt * 8 + tg * 2;
                uint32_t u = *(const uint32_t*)&g_xh[rowb + px];
                __nv_bfloat162 bp = *(__nv_bfloat162*)&u;
                float zx = lk(fmaf(__bfloat162float(bp.x), A0, B0)) + acc[nt][r * 2] + bb;
                float zy = lk(fmaf(__bfloat162float(bp.y), A0, B0)) + acc[nt][r * 2 + 1] + bb;
                *(uint32_t*)&g_zh[rowb + px] = packbf(zx, zy);
                ps[r] += zx + zy;
                pq[r] += zx * zx + zy * zy;
            }
        }
    }

#pragma unroll
    for (int r = 0; r < 2; r++) {
        ps[r] += __shfl_xor_sync(0xffffffffu, ps[r], 1);
        ps[r] += __shfl_xor_sync(0xffffffffu, ps[r], 2);
        pq[r] += __shfl_xor_sync(0xffffffffu, pq[r], 1);
        pq[r] += __shfl_xor_sync(0xffffffffu, pq[r], 2);
    }
    if ((lane & 3) == 0) {
#pragma unroll
        for (int r = 0; r < 2; r++) {
            const int co = mg * 16 + r * 8 + g;
            atomicAdd(&s_st[co], ps[r]);
            atomicAdd(&s_st[64 + co], pq[r]);
        }
    }
    __syncthreads();
    if (tid < 128) atomicAdd(&g_sum1[tid], s_st[tid]);
}

// ---------------- spatial mean of leaky(bn1(z)), coef1 inline ----------------
__global__ void __launch_bounds__(256) k_mean(const float* __restrict__ bn1g,
                                              const float* __restrict__ bn1b) {
    const int bid = blockIdx.x;
    const int c = (bid >> 3) & 63;
    const float inv = 1.0f / CNT_;
    const float mu = g_sum1[c] * inv;
    const float var = g_sum1[64 + c] * inv - mu * mu;
    const float A = bn1g[c] * rsqrtf(var + 1e-5f);
    const float Bv = bn1b[c] - mu * A;
    const uint32_t* p = (const uint32_t*)(g_zh + (size_t)bid * S_);
    float s = 0.f;
    for (int i = threadIdx.x; i < S_ / 2; i += 256) {
        uint32_t u = p[i];
        __nv_bfloat162 bp = *(__nv_bfloat162*)&u;
        s += lk(fmaf(__bfloat162float(bp.x), A, Bv));
        s += lk(fmaf(__bfloat162float(bp.y), A, Bv));
    }
#pragma unroll
    for (int off = 16; off; off >>= 1) s += __shfl_down_sync(0xffffffffu, s, off);
    __shared__ float wa[8];
    const int lane = threadIdx.x & 31, wid = threadIdx.x >> 5;
    if (lane == 0) wa[wid] = s;
    __syncthreads();
    if (threadIdx.x == 0) {
        float ts = 0.f;
#pragma unroll
        for (int i = 0; i < 8; i++) ts += wa[i];
        g_m[bid] = ts * (1.0f / (float)S_);
    }
}

// ---------------- dynamic depthwise 5x5 conv (kernel-gen fused) ----------------
__global__ void __launch_bounds__(256) k_dynconv(const float* __restrict__ h,
                                                 const float* __restrict__ w1,
                                                 const float* __restrict__ b1,
                                                 float* __restrict__ out) {
    __shared__ float sp[100 * 100];
    __shared__ float sk[25];
    const int bid = blockIdx.x;
    const int b = bid >> 9;
    const int t = bid & 7;
    const int tid = threadIdx.x;
    const float* base = h + (size_t)bid * S_;

    for (int i = tid; i < 10000; i += 256) sp[i] = 0.f;
    if (tid < 25) {
        float a = __ldg(&b1[tid]);
#pragma unroll 8
        for (int c = 0; c < 64; c++)
            a = fmaf(g_m[(b * C_ + c) * T_ + t], __ldg(&w1[tid * 64 + c]), a);
        sk[tid] = a;
    }
    __syncthreads();
    for (int i = tid; i < S_; i += 256) {
        const int r = i / 96, col = i - r * 96;
        sp[(r + 2) * 100 + col + 2] = base[i];
    }
    __syncthreads();

    float kr[25];
#pragma unroll
    for (int q = 0; q < 25; q++) kr[q] = sk[q];

    float* ob = out + (size_t)bid * S_;
    for (int i = tid; i < S_; i += 256) {
        const int r = i / 96, col = i - r * 96;
        const float* pp = &sp[r * 100 + col];
        float a = 0.f;
#pragma unroll
        for (int ii = 0; ii < 5; ii++)
#pragma unroll
            for (int jj = 0; jj < 5; jj++)
                a = fmaf(pp[ii * 100 + jj], kr[ii * 5 + jj], a);
        ob[i] = a;
    }
}

// ---------------- launch ----------------
extern "C" void kernel_launch(void* const* d_in, const int* in_sizes, int n_in,
                              void* d_out, int out_size) {
    const float* h       = (const float*)d_in[0];
    const float* conv0_w = (const float*)d_in[1];
    const float* conv0_b = (const float*)d_in[2];
    const float* bn0_g   = (const float*)d_in[3];
    const float* bn0_b   = (const float*)d_in[4];
    const float* bn1_g   = (const float*)d_in[5];
    const float* bn1_b   = (const float*)d_in[6];
    const float* inW     = (const float*)d_in[7];
    const float* inB     = (const float*)d_in[8];
    const float* outW    = (const float*)d_in[9];
    const float* outB    = (const float*)d_in[10];
    const float* c1w     = (const float*)d_in[11];
    const float* c1b     = (const float*)d_in[12];
    float* out = (float*)d_out;

    cudaFuncSetAttribute(k_conv0_mma, cudaFuncAttributeMaxDynamicSharedMemorySize,
                         SM_CONV_TOT);
    cudaFuncSetAttribute(k_qkv_mma, cudaFuncAttributeMaxDynamicSharedMemorySize,
                         QSM_TOT);
    cudaFuncSetAttribute(k_attn_fused, cudaFuncAttributeMaxDynamicSharedMemorySize,
                         SM_ATTN_TOT);

    k_prep<<<144, 256>>>(conv0_w, inW, outW);
    k_conv0_mma<<<dim3(4, B_ * T_), 512, SM_CONV_TOT>>>(h, conv0_b);
    k_qkv_mma<<<dim3(4, B_ * T_), 512, QSM_TOT>>>(inB, bn0_g, bn0_b);
    k_attn_fused<<<N_ / 64, 256, SM_ATTN_TOT>>>(outB, bn0_g, bn0_b);
    k_mean<<<B_ * C_ * T_, 256>>>(bn1_g, bn1_b);
    k_dynconv<<<B_ * C_ * T_, 256>>>(h, c1w, c1b, out);
}